// round 5
// baseline (speedup 1.0000x reference)
#include <cuda_runtime.h>
#include <math.h>
#include <stdint.h>

// ---------------- problem dims ----------------
#define MTOT   16384      // B*L = 16*1024
#define DMODEL 512
#define DLOW   256
#define DMH    258
#define DINNER 516
#define DSTATE 16
#define DTRANK 17
#define XDBL_C 49         // DTRANK + 2*DSTATE
#define FCOLS  514        // 2*257 packed freq channels
#define FLD    516        // padded leading dim for FCOLS buffers (16B-aligned rows)
#define XDLD   52         // padded leading dim for xdbl
#define LSEQ   1024
#define NB     16

// ---------------- scratch (device globals; no allocation allowed) ----------------
__device__ float g_FT[FCOLS * DMODEL];           // forward DFT weights (N=514, K=512) NT
__device__ float g_G [DMODEL * FLD];             // inverse DFT weights (N=512, K=514) NT, ld=516
__device__ float g_Wt[DLOW * 512];               // taylor weights (N=256, K=512) NT
__device__ float g_bias_t[DLOW];                 // taylor total bias
__device__ float g_xfcat[(size_t)MTOT * FLD + 64];  // rfft packed channels, ld=516
__device__ float g_feat [(size_t)MTOT * 512 + 64];  // [x_l, x_l^2]
__device__ float g_xz   [(size_t)MTOT * 1032 + 64]; // in_proj out
__device__ float g_xm   [(size_t)MTOT * DINNER + 64]; // conv+silu out
__device__ float g_xdbl [(size_t)MTOT * XDLD + 64];   // x_proj out, ld=52
__device__ float g_dt   [(size_t)MTOT * DINNER + 64]; // softplus(dt)
__device__ float g_ys   [(size_t)MTOT * DINNER + 64]; // scan out (gated)
__device__ float g_ycat [(size_t)MTOT * FLD + 64];    // [y_l | y_h], ld=516
__device__ float g_ymid [(size_t)MTOT * DMODEL + 64]; // irfft out (pre-norm)

// rfft ortho scale = 1/sqrt(512)
#define ORTHO_SCALE 0.04419417382415922f

// ---------------- fused weight prep (one launch) ----------------
// blocks [0,1028)            : FT gen        (256 thr)
// blocks [1028,2056)         : G gen         (256 thr)
// blocks [2056,2312)         : Wt build      (256 thr)
// blocks [2312,2344)         : bias build    (8 warps x 1 channel)
__global__ void k_prep(const float* __restrict__ coeffs,
                       const float* __restrict__ tb) {
    int blk = blockIdx.x;
    if (blk < 1028) {
        int idx = blk * 256 + threadIdx.x;
        if (idx >= FCOLS * DMODEL) return;
        int col = idx / DMODEL;
        int n   = idx - col * DMODEL;
        int k, isIm;
        if (col < 128)      { k = col;             isIm = 0; }
        else if (col < 256) { k = col - 128;       isIm = 1; }
        else if (col < 385) { k = col - 256 + 128; isIm = 0; }
        else                { k = col - 385 + 128; isIm = 1; }
        float a = (float)(k * n) * (1.0f / 256.0f);
        float s, c;
        sincospif(a, &s, &c);
        g_FT[(size_t)col * DMODEL + n] = isIm ? (-s * ORTHO_SCALE) : (c * ORTHO_SCALE);
    } else if (blk < 2056) {
        int idx = (blk - 1028) * 256 + threadIdx.x;
        if (idx >= DMODEL * FCOLS) return;
        int n = idx / FCOLS;
        int j = idx - n * FCOLS;
        int k = j >> 1;
        float a = (float)(k * n) * (1.0f / 256.0f);
        float s, c;
        sincospif(a, &s, &c);
        float val;
        if ((j & 1) == 0) {
            float w = (k == 0 || k == 256) ? 1.0f : 2.0f;
            val = w * c * ORTHO_SCALE;
        } else {
            val = (k == 0 || k == 256) ? 0.0f : (-2.0f * s * ORTHO_SCALE);
        }
        g_G[(size_t)n * FLD + j] = val;
    } else if (blk < 2312) {
        int idx = (blk - 2056) * 256 + threadIdx.x;
        if (idx >= DLOW * DLOW) return;
        int u = idx / DLOW;
        int i = idx - u * DLOW;
        const float* cp = coeffs + ((size_t)u * DLOW + i) * 3;
        g_Wt[(size_t)u * 512 + i]        = cp[1];
        g_Wt[(size_t)u * 512 + 256 + i]  = cp[2];
    } else {
        int u = (blk - 2312) * 8 + (threadIdx.x >> 5);   // 8 warps -> 8 channels
        int t = threadIdx.x & 31;
        if (u >= DLOW) return;
        float acc = 0.0f;
        const float* cp = coeffs + (size_t)u * DLOW * 3;
        for (int i = t; i < DLOW; i += 32) acc += cp[i * 3];
#pragma unroll
        for (int o = 16; o > 0; o >>= 1) acc += __shfl_xor_sync(0xffffffffu, acc, o);
        if (t == 0) g_bias_t[u] = acc + tb[u];
    }
}

// ---------------- 3xTF32 tensor-core NT GEMM, pre-split smem ----------------
// C[m,n] = sum_k A[m,k]*B[n,k].  BM=128, BN=64, BK=16, 256 threads.
// 8 warps tiled 4(M) x 2(N), warp tile 32x32, mma.m16n8k8 tf32, 3-pass split.
// Smem holds (hi,lo) tf32 pairs as uint2 -> hot loop has only LDS.64 + MMA.
// Requirements: M % 128 == 0; A rows 16B-aligned. N, K arbitrary (guarded).

__device__ __forceinline__ uint32_t f2tf(float x) {
    uint32_t r; asm("cvt.rna.tf32.f32 %0, %1;" : "=r"(r) : "f"(x)); return r;
}
__device__ __forceinline__ uint2 splitf2(float x) {
    uint32_t hi = f2tf(x);
    uint32_t lo = f2tf(x - __uint_as_float(hi));
    return make_uint2(hi, lo);
}

#define MMA_TF32(D, A0, A1, A2, A3, B0, B1)                                  \
    asm volatile("mma.sync.aligned.m16n8k8.row.col.f32.tf32.tf32.f32 "       \
                 "{%0,%1,%2,%3}, {%4,%5,%6,%7}, {%8,%9}, {%0,%1,%2,%3};"     \
                 : "+f"(D[0]), "+f"(D[1]), "+f"(D[2]), "+f"(D[3])            \
                 : "r"(A0), "r"(A1), "r"(A2), "r"(A3), "r"(B0), "r"(B1))

__global__ void __launch_bounds__(256, 2)
tgemm_nt(const float* __restrict__ A, int lda,
         const float* __restrict__ B, int ldb,
         float* __restrict__ C, int ldc,
         int N, int K,
         const float* __restrict__ bias, int act)
{
    __shared__ uint2 As[16][133];   // [k][m] (hi,lo); word-stride 266 = 10 mod 32
    __shared__ uint2 Bs[16][69];    // [k][n] (hi,lo); word-stride 138 = 10 mod 32

    const int tid = threadIdx.x;
    const int m0 = blockIdx.y * 128;
    const int n0 = blockIdx.x * 64;

    // A loader: thread -> (row am, k-offset ak), 2x float4
    const int am = tid >> 1;
    const int ak = (tid & 1) * 8;
    // B loader: thread -> (col bn, k-offset bk), 4 scalars
    const int bn = tid & 63;
    const int bk = (tid >> 6) * 4;

    const float* Arow = A + (size_t)(m0 + am) * lda;
    const float* Brow = B + (size_t)(n0 + bn) * ldb;
    const bool bval = (n0 + bn) < N;

    const int wid  = tid >> 5;
    const int lane = tid & 31;
    const int wm = (wid & 3) * 32;     // warp row offset in block tile
    const int wn = (wid >> 2) * 32;    // warp col offset
    const int grp = lane >> 2;
    const int qid = lane & 3;

    float acc[2][4][4];
#pragma unroll
    for (int i = 0; i < 2; i++)
#pragma unroll
        for (int j = 0; j < 4; j++)
#pragma unroll
            for (int r = 0; r < 4; r++) acc[i][j][r] = 0.0f;

    const int ntiles = (K + 15) >> 4;
    float a_reg[8];
    float b_reg[4];

#define LOAD_TILE(t)                                                          \
    {                                                                         \
        int k0 = (t) * 16;                                                    \
        if (k0 + 16 <= K) {                                                   \
            float4 v0 = *reinterpret_cast<const float4*>(Arow + k0 + ak);     \
            float4 v1 = *reinterpret_cast<const float4*>(Arow + k0 + ak + 4); \
            a_reg[0] = v0.x; a_reg[1] = v0.y; a_reg[2] = v0.z; a_reg[3] = v0.w;\
            a_reg[4] = v1.x; a_reg[5] = v1.y; a_reg[6] = v1.z; a_reg[7] = v1.w;\
            if (bval) {                                                       \
                b_reg[0] = Brow[k0 + bk + 0]; b_reg[1] = Brow[k0 + bk + 1];   \
                b_reg[2] = Brow[k0 + bk + 2]; b_reg[3] = Brow[k0 + bk + 3];   \
            } else { b_reg[0] = b_reg[1] = b_reg[2] = b_reg[3] = 0.0f; }      \
        } else {                                                              \
            _Pragma("unroll")                                                 \
            for (int c = 0; c < 8; c++) {                                     \
                int kk = k0 + ak + c;                                         \
                a_reg[c] = (kk < K) ? Arow[kk] : 0.0f;                        \
            }                                                                 \
            _Pragma("unroll")                                                 \
            for (int c = 0; c < 4; c++) {                                     \
                int kk = k0 + bk + c;                                         \
                b_reg[c] = (bval && kk < K) ? Brow[kk] : 0.0f;                \
            }                                                                 \
        }                                                                     \
    }

#define STORE_TILE()                                                          \
    {                                                                         \
        _Pragma("unroll")                                                     \
        for (int c = 0; c < 8; c++) As[ak + c][am] = splitf2(a_reg[c]);       \
        _Pragma("unroll")                                                     \
        for (int c = 0; c < 4; c++) Bs[bk + c][bn] = splitf2(b_reg[c]);       \
    }

    LOAD_TILE(0);

    for (int t = 0; t < ntiles; t++) {
        __syncthreads();   // previous compute done reading smem
        STORE_TILE();
        __syncthreads();
        if (t + 1 < ntiles) LOAD_TILE(t + 1);

        // ---- compute: pure LDS.64 + MMA ----
#pragma unroll
        for (int ks = 0; ks < 16; ks += 8) {
            uint2 b0[4], b1[4];
#pragma unroll
            for (int j = 0; j < 4; j++) {
                b0[j] = Bs[ks + qid][wn + j * 8 + grp];
                b1[j] = Bs[ks + qid + 4][wn + j * 8 + grp];
            }
#pragma unroll
            for (int i = 0; i < 2; i++) {
                uint2 a0 = As[ks + qid][wm + i * 16 + grp];
                uint2 a1 = As[ks + qid][wm + i * 16 + grp + 8];
                uint2 a2 = As[ks + qid + 4][wm + i * 16 + grp];
                uint2 a3 = As[ks + qid + 4][wm + i * 16 + grp + 8];
#pragma unroll
                for (int j = 0; j < 4; j++) {
                    MMA_TF32(acc[i][j], a0.x, a1.x, a2.x, a3.x, b0[j].x, b1[j].x);
                    MMA_TF32(acc[i][j], a0.x, a1.x, a2.x, a3.x, b0[j].y, b1[j].y);
                    MMA_TF32(acc[i][j], a0.y, a1.y, a2.y, a3.y, b0[j].x, b1[j].x);
                }
            }
        }
    }

    // ---- epilogue ----
#pragma unroll
    for (int i = 0; i < 2; i++) {
#pragma unroll
        for (int j = 0; j < 4; j++) {
            int r0 = m0 + wm + i * 16 + grp;
            int c0 = n0 + wn + j * 8 + qid * 2;
            float v[4] = {acc[i][j][0], acc[i][j][1], acc[i][j][2], acc[i][j][3]};
#pragma unroll
            for (int e = 0; e < 4; e++) {
                int n = c0 + (e & 1);
                if (n < N) {
                    float x = v[e];
                    if (bias) x += bias[n];
                    if (act == 1) x = fmaxf(x, 0.0f) + log1pf(__expf(-fabsf(x)));
                    C[(size_t)(r0 + (e >> 1) * 8) * ldc + n] = x;
                }
            }
        }
    }
}

// ---------------- taylor feature build: [x, x^2] ----------------
__global__ void k_feat() {
    int idx = blockIdx.x * blockDim.x + threadIdx.x;   // MTOT*256
    if (idx >= MTOT * DLOW) return;
    int m = idx / DLOW;
    int i = idx - m * DLOW;
    float v = g_xfcat[(size_t)m * FLD + i];
    g_feat[(size_t)m * 512 + i]       = v;
    g_feat[(size_t)m * 512 + 256 + i] = v * v;
}

// ---------------- depthwise causal conv(4) + silu ----------------
__global__ void k_conv_silu(const float* __restrict__ conv_w,
                            const float* __restrict__ conv_b) {
    int idx = blockIdx.x * blockDim.x + threadIdx.x;   // MTOT*DINNER
    if (idx >= MTOT * DINNER) return;
    int m = idx / DINNER;
    int d = idx - m * DINNER;
    int l = m & (LSEQ - 1);
    const float* w = conv_w + d * 4;
    float acc = conv_b[d];
#pragma unroll
    for (int j = 0; j < 4; j++) {
        int ls = l - 3 + j;
        if (ls >= 0) acc += g_xz[(size_t)(m - 3 + j) * 1032 + d] * w[j];
    }
    float sg = 1.0f / (1.0f + __expf(-acc));
    g_xm[(size_t)m * DINNER + d] = acc * sg;
}

// ---------------- selective scan (thread per (b,d,s), 16-lane reduce) ----------
__global__ void k_scan(const float* __restrict__ A_log,
                       const float* __restrict__ D_param) {
    int g = blockIdx.x * 8 + (threadIdx.x >> 4);   // group index over (b,d)
    int s = threadIdx.x & 15;
    if (g >= NB * DINNER) return;
    int b = g / DINNER;
    int d = g - b * DINNER;

    const float A  = -__expf(A_log[d * DSTATE + s]);
    const float Dv = D_param[d];

    const size_t rowb = (size_t)b * LSEQ;
    const float* dtp = g_dt   + rowb * DINNER + d;
    const float* xp  = g_xm   + rowb * DINNER + d;
    const float* Bp  = g_xdbl + rowb * XDLD + DTRANK + s;
    const float* Cp  = g_xdbl + rowb * XDLD + DTRANK + DSTATE + s;
    const float* zp  = g_xz   + rowb * 1032 + DINNER + d;
    float*       yp  = g_ys   + rowb * DINNER + d;

    float h = 0.0f;
    for (int t = 0; t < LSEQ; t++) {
        float dtv = dtp[(size_t)t * DINNER];
        float xv  = xp [(size_t)t * DINNER];
        float Bv  = Bp [(size_t)t * XDLD];
        float Cv  = Cp [(size_t)t * XDLD];
        h = __expf(dtv * A) * h + (dtv * xv) * Bv;
        float p = h * Cv;
        p += __shfl_xor_sync(0xffffffffu, p, 1);
        p += __shfl_xor_sync(0xffffffffu, p, 2);
        p += __shfl_xor_sync(0xffffffffu, p, 4);
        p += __shfl_xor_sync(0xffffffffu, p, 8);
        if (s == 0) {
            float zv = zp[(size_t)t * 1032];
            float sg = 1.0f / (1.0f + __expf(-zv));
            yp[(size_t)t * DINNER] = (p + xv * Dv) * (zv * sg);
        }
    }
}

// ---------------- RMSNorm * w + residual ----------------
__global__ void k_norm(const float* __restrict__ x,
                       const float* __restrict__ nw,
                       float* __restrict__ out) {
    int m = blockIdx.x;
    const float* yr = g_ymid + (size_t)m * DMODEL;
    float v[4];
    float ss = 0.0f;
#pragma unroll
    for (int i = 0; i < 4; i++) {
        v[i] = yr[threadIdx.x + i * 128];
        ss += v[i] * v[i];
    }
    __shared__ float red[4];
#pragma unroll
    for (int o = 16; o > 0; o >>= 1) ss += __shfl_xor_sync(0xffffffffu, ss, o);
    if ((threadIdx.x & 31) == 0) red[threadIdx.x >> 5] = ss;
    __syncthreads();
    float tot = red[0] + red[1] + red[2] + red[3];
    float rs = rsqrtf(tot * (1.0f / DMODEL) + 1e-5f);
#pragma unroll
    for (int i = 0; i < 4; i++) {
        int n = threadIdx.x + i * 128;
        out[(size_t)m * DMODEL + n] = v[i] * rs * nw[n] + x[(size_t)m * DMODEL + n];
    }
}

// ---------------- launch ----------------
static inline dim3 tg_grid(int N) { return dim3((N + 63) / 64, MTOT / 128); }

extern "C" void kernel_launch(void* const* d_in, const int* in_sizes, int n_in,
                              void* d_out, int out_size) {
    const float* x             = (const float*)d_in[0];
    const float* taylor_coeffs = (const float*)d_in[1];
    const float* taylor_bias   = (const float*)d_in[2];
    const float* in_proj_w     = (const float*)d_in[3];
    const float* conv_w        = (const float*)d_in[4];
    const float* conv_b        = (const float*)d_in[5];
    const float* x_proj_w      = (const float*)d_in[6];
    const float* dt_proj_w     = (const float*)d_in[7];
    const float* dt_proj_b     = (const float*)d_in[8];
    const float* A_log         = (const float*)d_in[9];
    const float* D_param       = (const float*)d_in[10];
    const float* out_proj_w    = (const float*)d_in[11];
    const float* norm_w        = (const float*)d_in[12];
    float* out = (float*)d_out;

    float *p_FT, *p_G, *p_Wt, *p_bias, *p_xfcat, *p_feat, *p_xz, *p_xm,
          *p_xdbl, *p_dt, *p_ys, *p_ycat, *p_ymid;
    cudaGetSymbolAddress((void**)&p_FT,    g_FT);
    cudaGetSymbolAddress((void**)&p_G,     g_G);
    cudaGetSymbolAddress((void**)&p_Wt,    g_Wt);
    cudaGetSymbolAddress((void**)&p_bias,  g_bias_t);
    cudaGetSymbolAddress((void**)&p_xfcat, g_xfcat);
    cudaGetSymbolAddress((void**)&p_feat,  g_feat);
    cudaGetSymbolAddress((void**)&p_xz,    g_xz);
    cudaGetSymbolAddress((void**)&p_xm,    g_xm);
    cudaGetSymbolAddress((void**)&p_xdbl,  g_xdbl);
    cudaGetSymbolAddress((void**)&p_dt,    g_dt);
    cudaGetSymbolAddress((void**)&p_ys,    g_ys);
    cudaGetSymbolAddress((void**)&p_ycat,  g_ycat);
    cudaGetSymbolAddress((void**)&p_ymid,  g_ymid);

    // 1) fused weight prep (one launch)
    k_prep<<<2344, 256>>>(taylor_coeffs, taylor_bias);

    // 2) forward DFT: xfcat = x @ FT^T   (M,514), ldc=516
    tgemm_nt<<<tg_grid(FCOLS), 256>>>(x, DMODEL, p_FT, DMODEL,
                                      p_xfcat, FLD, FCOLS, DMODEL, nullptr, 0);
    // 3) taylor features + GEMM -> ycat[:, 0:256]
    k_feat<<<(MTOT * DLOW + 255) / 256, 256>>>();
    tgemm_nt<<<tg_grid(DLOW), 256>>>(p_feat, 512, p_Wt, 512,
                                     p_ycat, FLD, DLOW, 512, p_bias, 0);
    // 4) mamba in_proj: xz = xh_cat @ in_proj_w^T  (M,1032)
    tgemm_nt<<<tg_grid(1032), 256>>>(p_xfcat + 256, FLD, in_proj_w, DMH,
                                     p_xz, 1032, 1032, DMH, nullptr, 0);
    // 5) conv + silu -> xm
    k_conv_silu<<<(MTOT * DINNER + 255) / 256, 256>>>(conv_w, conv_b);
    // 6) x_proj: xdbl = xm @ x_proj_w^T  (M,49), ldc=52
    tgemm_nt<<<tg_grid(XDBL_C), 256>>>(p_xm, DINNER, x_proj_w, DINNER,
                                       p_xdbl, XDLD, XDBL_C, DINNER, nullptr, 0);
    // 7) dt: softplus(xdbl[:, :17] @ dt_proj_w^T + b)  (M,516)
    tgemm_nt<<<tg_grid(DINNER), 256>>>(p_xdbl, XDLD, dt_proj_w, DTRANK,
                                       p_dt, DINNER, DINNER, DTRANK, dt_proj_b, 1);
    // 8) selective scan (fused +x*D and silu(z) gate) -> ys
    k_scan<<<(NB * DINNER + 7) / 8, 128>>>(A_log, D_param);
    // 9) out_proj -> ycat[:, 256:514]
    tgemm_nt<<<tg_grid(DMH), 256>>>(p_ys, DINNER, out_proj_w, DINNER,
                                    p_ycat + 256, FLD, DMH, DINNER, nullptr, 0);
    // 10) inverse DFT: ymid = ycat @ G^T  (M,512), lda=ldb=516, K=514
    tgemm_nt<<<tg_grid(DMODEL), 256>>>(p_ycat, FLD, p_G, FLD,
                                       p_ymid, DMODEL, DMODEL, FCOLS, nullptr, 0);
    // 11) RMSNorm + residual
    k_norm<<<MTOT, 128>>>(x, norm_w, out);
}

// round 7
// speedup vs baseline: 1.0540x; 1.0540x over previous
#include <cuda_runtime.h>
#include <math.h>
#include <stdint.h>

// ---------------- problem dims ----------------
#define MTOT   16384      // B*L = 16*1024
#define DMODEL 512
#define DLOW   256
#define DMH    258
#define DINNER 516
#define DSTATE 16
#define DTRANK 17
#define XDBL_C 49         // DTRANK + 2*DSTATE
#define FCOLS  514        // 2*257 packed freq channels
#define FLD    516        // padded leading dim for FCOLS buffers (16B-aligned rows)
#define XDLD   52         // padded leading dim for xdbl
#define LSEQ   1024
#define NB     16

// ---------------- scratch (device globals; no allocation allowed) ----------------
__device__ float g_FT[FCOLS * DMODEL];           // forward DFT weights (N=514, K=512) NT
__device__ float g_G [DMODEL * FLD];             // inverse DFT weights (N=512, K=514) NT, ld=516
__device__ float g_Wt[DLOW * 512];               // taylor weights (N=256, K=512) NT
__device__ float g_bias_t[DLOW];                 // taylor total bias
__device__ float g_xfcat[(size_t)MTOT * FLD + 64];  // rfft packed channels, ld=516
__device__ float g_feat [(size_t)MTOT * 512 + 64];  // [x_l, x_l^2]
__device__ float g_xz   [(size_t)MTOT * 1032 + 64]; // in_proj out
__device__ float g_xm   [(size_t)MTOT * DINNER + 64]; // conv+silu out
__device__ float g_xdbl [(size_t)MTOT * XDLD + 64];   // x_proj out, ld=52
__device__ float g_dt   [(size_t)MTOT * DINNER + 64]; // softplus(dt)
__device__ float g_ys   [(size_t)MTOT * DINNER + 64]; // scan out (gated)
__device__ float g_ycat [(size_t)MTOT * FLD + 64];    // [y_l | y_h], ld=516
__device__ float g_ymid [(size_t)MTOT * DMODEL + 64]; // irfft out (pre-norm)

// rfft ortho scale = 1/sqrt(512)
#define ORTHO_SCALE 0.04419417382415922f

// ---------------- fused weight prep (one launch) ----------------
__global__ void k_prep(const float* __restrict__ coeffs,
                       const float* __restrict__ tb) {
    int blk = blockIdx.x;
    if (blk < 1028) {
        int idx = blk * 256 + threadIdx.x;
        if (idx >= FCOLS * DMODEL) return;
        int col = idx / DMODEL;
        int n   = idx - col * DMODEL;
        int k, isIm;
        if (col < 128)      { k = col;             isIm = 0; }
        else if (col < 256) { k = col - 128;       isIm = 1; }
        else if (col < 385) { k = col - 256 + 128; isIm = 0; }
        else                { k = col - 385 + 128; isIm = 1; }
        float a = (float)(k * n) * (1.0f / 256.0f);
        float s, c;
        sincospif(a, &s, &c);
        g_FT[(size_t)col * DMODEL + n] = isIm ? (-s * ORTHO_SCALE) : (c * ORTHO_SCALE);
    } else if (blk < 2056) {
        int idx = (blk - 1028) * 256 + threadIdx.x;
        if (idx >= DMODEL * FCOLS) return;
        int n = idx / FCOLS;
        int j = idx - n * FCOLS;
        int k = j >> 1;
        float a = (float)(k * n) * (1.0f / 256.0f);
        float s, c;
        sincospif(a, &s, &c);
        float val;
        if ((j & 1) == 0) {
            float w = (k == 0 || k == 256) ? 1.0f : 2.0f;
            val = w * c * ORTHO_SCALE;
        } else {
            val = (k == 0 || k == 256) ? 0.0f : (-2.0f * s * ORTHO_SCALE);
        }
        g_G[(size_t)n * FLD + j] = val;
    } else if (blk < 2312) {
        int idx = (blk - 2056) * 256 + threadIdx.x;
        if (idx >= DLOW * DLOW) return;
        int u = idx / DLOW;
        int i = idx - u * DLOW;
        const float* cp = coeffs + ((size_t)u * DLOW + i) * 3;
        g_Wt[(size_t)u * 512 + i]        = cp[1];
        g_Wt[(size_t)u * 512 + 256 + i]  = cp[2];
    } else {
        int u = (blk - 2312) * 8 + (threadIdx.x >> 5);
        int t = threadIdx.x & 31;
        if (u >= DLOW) return;
        float acc = 0.0f;
        const float* cp = coeffs + (size_t)u * DLOW * 3;
        for (int i = t; i < DLOW; i += 32) acc += cp[i * 3];
#pragma unroll
        for (int o = 16; o > 0; o >>= 1) acc += __shfl_xor_sync(0xffffffffu, acc, o);
        if (t == 0) g_bias_t[u] = acc + tb[u];
    }
}

// ---------------- 3xTF32 tensor-core NT GEMM, pre-split swizzled smem ----------
// C[m,n] = sum_k A[m,k]*B[n,k].  BM=128, BN=64, BK=16, 256 threads, double-buffered.
// Smem uint2 (tf32 hi,lo), XOR swizzle col^( (k&3)<<2 ), strides exactly 128/64
// -> conflict-free LDS.64/STS.64, total smem = 48KB, 2 CTA/SM.
// act: 0=none, 1=softplus(+bias), 2=also write [v, v*v] to aux (taylor feat fusion)

__device__ __forceinline__ uint32_t f2tf(float x) {
    uint32_t r; asm("cvt.rna.tf32.f32 %0, %1;" : "=r"(r) : "f"(x)); return r;
}
__device__ __forceinline__ uint2 splitf2(float x) {
    uint32_t hi = f2tf(x);
    uint32_t lo = f2tf(x - __uint_as_float(hi));
    return make_uint2(hi, lo);
}

#define MMA_TF32(D, A0, A1, A2, A3, B0, B1)                                  \
    asm volatile("mma.sync.aligned.m16n8k8.row.col.f32.tf32.tf32.f32 "       \
                 "{%0,%1,%2,%3}, {%4,%5,%6,%7}, {%8,%9}, {%0,%1,%2,%3};"     \
                 : "+f"(D[0]), "+f"(D[1]), "+f"(D[2]), "+f"(D[3])            \
                 : "r"(A0), "r"(A1), "r"(A2), "r"(A3), "r"(B0), "r"(B1))

__global__ void __launch_bounds__(256, 2)
tgemm_nt(const float* __restrict__ A, int lda,
         const float* __restrict__ B, int ldb,
         float* __restrict__ C, int ldc,
         int N, int K,
         const float* __restrict__ bias, int act,
         float* __restrict__ aux)
{
    __shared__ uint2 As[2][16][128];   // 32 KB
    __shared__ uint2 Bs[2][16][64];    // 16 KB

    const int tid = threadIdx.x;
    const int m0 = blockIdx.y * 128;
    const int n0 = blockIdx.x * 64;

    // A loader: row am = tid&127, k-offset ak = (tid>>7)*8 (2x float4)
    const int am = tid & 127;
    const int ak = (tid >> 7) * 8;
    // B loader: col bn = tid&63, k-offset bk = (tid>>6)*4
    const int bn = tid & 63;
    const int bk = (tid >> 6) * 4;

    const float* Arow = A + (size_t)(m0 + am) * lda;
    const float* Brow = B + (size_t)(n0 + bn) * ldb;
    const bool bval = (n0 + bn) < N;

    const int wid  = tid >> 5;
    const int lane = tid & 31;
    const int wm = (wid & 3) * 32;     // warp row offset
    const int wn = (wid >> 2) * 32;    // warp col offset
    const int grp = lane >> 2;
    const int qid = lane & 3;
    const int sw  = qid << 2;          // fragment-load swizzle

    float acc[2][4][4];
#pragma unroll
    for (int i = 0; i < 2; i++)
#pragma unroll
        for (int j = 0; j < 4; j++)
#pragma unroll
            for (int r = 0; r < 4; r++) acc[i][j][r] = 0.0f;

    const int ntiles = (K + 15) >> 4;
    float a_reg[8];
    float b_reg[4];

#define LOAD_TILE(t)                                                          \
    {                                                                         \
        int k0 = (t) * 16;                                                    \
        if (k0 + 16 <= K) {                                                   \
            float4 v0 = *reinterpret_cast<const float4*>(Arow + k0 + ak);     \
            float4 v1 = *reinterpret_cast<const float4*>(Arow + k0 + ak + 4); \
            a_reg[0] = v0.x; a_reg[1] = v0.y; a_reg[2] = v0.z; a_reg[3] = v0.w;\
            a_reg[4] = v1.x; a_reg[5] = v1.y; a_reg[6] = v1.z; a_reg[7] = v1.w;\
            if (bval) {                                                       \
                b_reg[0] = Brow[k0 + bk + 0]; b_reg[1] = Brow[k0 + bk + 1];   \
                b_reg[2] = Brow[k0 + bk + 2]; b_reg[3] = Brow[k0 + bk + 3];   \
            } else { b_reg[0] = b_reg[1] = b_reg[2] = b_reg[3] = 0.0f; }      \
        } else {                                                              \
            _Pragma("unroll")                                                 \
            for (int c = 0; c < 8; c++) {                                     \
                int kk = k0 + ak + c;                                         \
                a_reg[c] = (kk < K) ? Arow[kk] : 0.0f;                        \
            }                                                                 \
            _Pragma("unroll")                                                 \
            for (int c = 0; c < 4; c++) {                                     \
                int kk = k0 + bk + c;                                         \
                b_reg[c] = (bval && kk < K) ? Brow[kk] : 0.0f;                \
            }                                                                 \
        }                                                                     \
    }

#define STORE_TILE(buf)                                                       \
    {                                                                         \
        _Pragma("unroll")                                                     \
        for (int c = 0; c < 8; c++)                                           \
            As[buf][ak + c][am ^ (((ak + c) & 3) << 2)] = splitf2(a_reg[c]);  \
        _Pragma("unroll")                                                     \
        for (int c = 0; c < 4; c++)                                           \
            Bs[buf][bk + c][bn ^ (((bk + c) & 3) << 2)] = splitf2(b_reg[c]);  \
    }

    LOAD_TILE(0);
    STORE_TILE(0);
    __syncthreads();

    int cur = 0;
    for (int t = 0; t < ntiles; t++) {
        if (t + 1 < ntiles) LOAD_TILE(t + 1);

        // ---- compute on buffer cur: pure LDS.64 + MMA (conflict-free) ----
#pragma unroll
        for (int ks = 0; ks < 16; ks += 8) {
            uint2 b0[4], b1[4];
#pragma unroll
            for (int j = 0; j < 4; j++) {
                b0[j] = Bs[cur][ks + qid][(wn + j * 8 + grp) ^ sw];
                b1[j] = Bs[cur][ks + qid + 4][(wn + j * 8 + grp) ^ sw];
            }
#pragma unroll
            for (int i = 0; i < 2; i++) {
                uint2 a0 = As[cur][ks + qid][(wm + i * 16 + grp) ^ sw];
                uint2 a1 = As[cur][ks + qid][(wm + i * 16 + grp + 8) ^ sw];
                uint2 a2 = As[cur][ks + qid + 4][(wm + i * 16 + grp) ^ sw];
                uint2 a3 = As[cur][ks + qid + 4][(wm + i * 16 + grp + 8) ^ sw];
#pragma unroll
                for (int j = 0; j < 4; j++) {
                    MMA_TF32(acc[i][j], a0.x, a1.x, a2.x, a3.x, b0[j].x, b1[j].x);
                    MMA_TF32(acc[i][j], a0.x, a1.x, a2.x, a3.x, b0[j].y, b1[j].y);
                    MMA_TF32(acc[i][j], a0.y, a1.y, a2.y, a3.y, b0[j].x, b1[j].x);
                }
            }
        }

        if (t + 1 < ntiles) {
            STORE_TILE(cur ^ 1);
            __syncthreads();
            cur ^= 1;
        }
    }

    // ---- epilogue ----
#pragma unroll
    for (int i = 0; i < 2; i++) {
#pragma unroll
        for (int j = 0; j < 4; j++) {
            int r0 = m0 + wm + i * 16 + grp;
            int c0 = n0 + wn + j * 8 + qid * 2;
            float v[4] = {acc[i][j][0], acc[i][j][1], acc[i][j][2], acc[i][j][3]};
#pragma unroll
            for (int e = 0; e < 4; e++) {
                int n = c0 + (e & 1);
                int r = r0 + (e >> 1) * 8;
                if (n < N) {
                    float x = v[e];
                    if (bias) x += bias[n];
                    if (act == 1) x = fmaxf(x, 0.0f) + log1pf(__expf(-fabsf(x)));
                    C[(size_t)r * ldc + n] = x;
                    if (act == 2 && n < DLOW) {
                        aux[(size_t)r * 512 + n]        = x;
                        aux[(size_t)r * 512 + 256 + n]  = x * x;
                    }
                }
            }
        }
    }
}

// ---------------- depthwise causal conv(4) + silu ----------------
__global__ void k_conv_silu(const float* __restrict__ conv_w,
                            const float* __restrict__ conv_b) {
    int idx = blockIdx.x * blockDim.x + threadIdx.x;   // MTOT*DINNER
    if (idx >= MTOT * DINNER) return;
    int m = idx / DINNER;
    int d = idx - m * DINNER;
    int l = m & (LSEQ - 1);
    const float* w = conv_w + d * 4;
    float acc = conv_b[d];
#pragma unroll
    for (int j = 0; j < 4; j++) {
        int ls = l - 3 + j;
        if (ls >= 0) acc += g_xz[(size_t)(m - 3 + j) * 1032 + d] * w[j];
    }
    float sg = 1.0f / (1.0f + __expf(-acc));
    g_xm[(size_t)m * DINNER + d] = acc * sg;
}

// ---------------- selective scan (thread per (b,d,s), 16-lane reduce) ----------
__global__ void k_scan(const float* __restrict__ A_log,
                       const float* __restrict__ D_param) {
    int g = blockIdx.x * 8 + (threadIdx.x >> 4);
    int s = threadIdx.x & 15;
    if (g >= NB * DINNER) return;
    int b = g / DINNER;
    int d = g - b * DINNER;

    const float A  = -__expf(A_log[d * DSTATE + s]);
    const float Dv = D_param[d];

    const size_t rowb = (size_t)b * LSEQ;
    const float* dtp = g_dt   + rowb * DINNER + d;
    const float* xp  = g_xm   + rowb * DINNER + d;
    const float* Bp  = g_xdbl + rowb * XDLD + DTRANK + s;
    const float* Cp  = g_xdbl + rowb * XDLD + DTRANK + DSTATE + s;
    const float* zp  = g_xz   + rowb * 1032 + DINNER + d;
    float*       yp  = g_ys   + rowb * DINNER + d;

    float h = 0.0f;
    for (int t = 0; t < LSEQ; t++) {
        float dtv = dtp[(size_t)t * DINNER];
        float xv  = xp [(size_t)t * DINNER];
        float Bv  = Bp [(size_t)t * XDLD];
        float Cv  = Cp [(size_t)t * XDLD];
        h = __expf(dtv * A) * h + (dtv * xv) * Bv;
        float p = h * Cv;
        p += __shfl_xor_sync(0xffffffffu, p, 1);
        p += __shfl_xor_sync(0xffffffffu, p, 2);
        p += __shfl_xor_sync(0xffffffffu, p, 4);
        p += __shfl_xor_sync(0xffffffffu, p, 8);
        if (s == 0) {
            float zv = zp[(size_t)t * 1032];
            float sg = 1.0f / (1.0f + __expf(-zv));
            yp[(size_t)t * DINNER] = (p + xv * Dv) * (zv * sg);
        }
    }
}

// ---------------- RMSNorm * w + residual ----------------
__global__ void k_norm(const float* __restrict__ x,
                       const float* __restrict__ nw,
                       float* __restrict__ out) {
    int m = blockIdx.x;
    const float* yr = g_ymid + (size_t)m * DMODEL;
    float v[4];
    float ss = 0.0f;
#pragma unroll
    for (int i = 0; i < 4; i++) {
        v[i] = yr[threadIdx.x + i * 128];
        ss += v[i] * v[i];
    }
    __shared__ float red[4];
#pragma unroll
    for (int o = 16; o > 0; o >>= 1) ss += __shfl_xor_sync(0xffffffffu, ss, o);
    if ((threadIdx.x & 31) == 0) red[threadIdx.x >> 5] = ss;
    __syncthreads();
    float tot = red[0] + red[1] + red[2] + red[3];
    float rs = rsqrtf(tot * (1.0f / DMODEL) + 1e-5f);
#pragma unroll
    for (int i = 0; i < 4; i++) {
        int n = threadIdx.x + i * 128;
        out[(size_t)m * DMODEL + n] = v[i] * rs * nw[n] + x[(size_t)m * DMODEL + n];
    }
}

// ---------------- launch ----------------
static inline dim3 tg_grid(int N) { return dim3((N + 63) / 64, MTOT / 128); }

extern "C" void kernel_launch(void* const* d_in, const int* in_sizes, int n_in,
                              void* d_out, int out_size) {
    const float* x             = (const float*)d_in[0];
    const float* taylor_coeffs = (const float*)d_in[1];
    const float* taylor_bias   = (const float*)d_in[2];
    const float* in_proj_w     = (const float*)d_in[3];
    const float* conv_w        = (const float*)d_in[4];
    const float* conv_b        = (const float*)d_in[5];
    const float* x_proj_w      = (const float*)d_in[6];
    const float* dt_proj_w     = (const float*)d_in[7];
    const float* dt_proj_b     = (const float*)d_in[8];
    const float* A_log         = (const float*)d_in[9];
    const float* D_param       = (const float*)d_in[10];
    const float* out_proj_w    = (const float*)d_in[11];
    const float* norm_w        = (const float*)d_in[12];
    float* out = (float*)d_out;

    float *p_FT, *p_G, *p_Wt, *p_bias, *p_xfcat, *p_feat, *p_xz, *p_xm,
          *p_xdbl, *p_dt, *p_ys, *p_ycat, *p_ymid;
    cudaGetSymbolAddress((void**)&p_FT,    g_FT);
    cudaGetSymbolAddress((void**)&p_G,     g_G);
    cudaGetSymbolAddress((void**)&p_Wt,    g_Wt);
    cudaGetSymbolAddress((void**)&p_bias,  g_bias_t);
    cudaGetSymbolAddress((void**)&p_xfcat, g_xfcat);
    cudaGetSymbolAddress((void**)&p_feat,  g_feat);
    cudaGetSymbolAddress((void**)&p_xz,    g_xz);
    cudaGetSymbolAddress((void**)&p_xm,    g_xm);
    cudaGetSymbolAddress((void**)&p_xdbl,  g_xdbl);
    cudaGetSymbolAddress((void**)&p_dt,    g_dt);
    cudaGetSymbolAddress((void**)&p_ys,    g_ys);
    cudaGetSymbolAddress((void**)&p_ycat,  g_ycat);
    cudaGetSymbolAddress((void**)&p_ymid,  g_ymid);

    // 1) fused weight prep
    k_prep<<<2344, 256>>>(taylor_coeffs, taylor_bias);

    // 2) forward DFT (+ fused taylor-feature build): xfcat = x @ FT^T
    tgemm_nt<<<tg_grid(FCOLS), 256>>>(x, DMODEL, p_FT, DMODEL,
                                      p_xfcat, FLD, FCOLS, DMODEL, nullptr, 2, p_feat);
    // 3) taylor GEMM -> ycat[:, 0:256]
    tgemm_nt<<<tg_grid(DLOW), 256>>>(p_feat, 512, p_Wt, 512,
                                     p_ycat, FLD, DLOW, 512, p_bias, 0, nullptr);
    // 4) mamba in_proj: xz = xh_cat @ in_proj_w^T  (M,1032)
    tgemm_nt<<<tg_grid(1032), 256>>>(p_xfcat + 256, FLD, in_proj_w, DMH,
                                     p_xz, 1032, 1032, DMH, nullptr, 0, nullptr);
    // 5) conv + silu -> xm
    k_conv_silu<<<(MTOT * DINNER + 255) / 256, 256>>>(conv_w, conv_b);
    // 6) x_proj: xdbl = xm @ x_proj_w^T  (M,49), ldc=52
    tgemm_nt<<<tg_grid(XDBL_C), 256>>>(p_xm, DINNER, x_proj_w, DINNER,
                                       p_xdbl, XDLD, XDBL_C, DINNER, nullptr, 0, nullptr);
    // 7) dt: softplus(xdbl[:, :17] @ dt_proj_w^T + b)  (M,516)
    tgemm_nt<<<tg_grid(DINNER), 256>>>(p_xdbl, XDLD, dt_proj_w, DTRANK,
                                       p_dt, DINNER, DINNER, DTRANK, dt_proj_b, 1, nullptr);
    // 8) selective scan (fused +x*D and silu(z) gate) -> ys
    k_scan<<<(NB * DINNER + 7) / 8, 128>>>(A_log, D_param);
    // 9) out_proj -> ycat[:, 256:514]
    tgemm_nt<<<tg_grid(DMH), 256>>>(p_ys, DINNER, out_proj_w, DINNER,
                                    p_ycat + 256, FLD, DMH, DINNER, nullptr, 0, nullptr);
    // 10) inverse DFT: ymid = ycat @ G^T  (M,512)
    tgemm_nt<<<tg_grid(DMODEL), 256>>>(p_ycat, FLD, p_G, FLD,
                                       p_ymid, DMODEL, DMODEL, FCOLS, nullptr, 0, nullptr);
    // 11) RMSNorm + residual
    k_norm<<<MTOT, 128>>>(x, norm_w, out);
}

// round 8
// speedup vs baseline: 1.1914x; 1.1303x over previous
#include <cuda_runtime.h>
#include <math.h>
#include <stdint.h>

// ---------------- problem dims ----------------
#define MTOT   16384      // B*L = 16*1024
#define DMODEL 512
#define DLOW   256
#define DMH    258
#define DINNER 516
#define DSTATE 16
#define DTRANK 17
#define XDBL_C 49         // DTRANK + 2*DSTATE
#define FCOLS  514        // 2*257 packed freq channels
#define FLD    516        // padded leading dim for FCOLS buffers (16B-aligned rows)
#define XDLD   52         // padded leading dim for xdbl
#define LSEQ   1024
#define NB     16

// ---------------- scratch (device globals; no allocation allowed) ----------------
__device__ float g_FT[FCOLS * DMODEL];           // forward DFT weights (N=514, K=512) NT
__device__ float g_G [DMODEL * FLD];             // inverse DFT weights (N=512, K=514) NT, ld=516
__device__ float g_Wt[DLOW * 512];               // taylor weights (N=256, K=512) NT
__device__ float g_bias_t[DLOW];                 // taylor total bias
__device__ float g_xfcat[(size_t)MTOT * FLD + 64];  // rfft packed channels, ld=516
__device__ float g_feat [(size_t)MTOT * 512 + 64];  // [x_l, x_l^2]
__device__ float g_xz   [(size_t)MTOT * 1032 + 64]; // in_proj out
__device__ float g_xm   [(size_t)MTOT * DINNER + 64]; // conv+silu out
__device__ float g_xdbl [(size_t)MTOT * XDLD + 64];   // x_proj out, ld=52
__device__ float g_dt   [(size_t)MTOT * DINNER + 64]; // softplus(dt)
__device__ float g_ys   [(size_t)MTOT * DINNER + 64]; // scan out (gated)
__device__ float g_ycat [(size_t)MTOT * FLD + 64];    // [y_l | y_h], ld=516
__device__ float g_ymid [(size_t)MTOT * DMODEL + 64]; // irfft out (pre-norm)

// rfft ortho scale = 1/sqrt(512)
#define ORTHO_SCALE 0.04419417382415922f

// ---------------- fused weight prep (one launch) ----------------
__global__ void k_prep(const float* __restrict__ coeffs,
                       const float* __restrict__ tb) {
    int blk = blockIdx.x;
    if (blk < 1028) {
        int idx = blk * 256 + threadIdx.x;
        if (idx >= FCOLS * DMODEL) return;
        int col = idx / DMODEL;
        int n   = idx - col * DMODEL;
        int k, isIm;
        if (col < 128)      { k = col;             isIm = 0; }
        else if (col < 256) { k = col - 128;       isIm = 1; }
        else if (col < 385) { k = col - 256 + 128; isIm = 0; }
        else                { k = col - 385 + 128; isIm = 1; }
        float a = (float)(k * n) * (1.0f / 256.0f);
        float s, c;
        sincospif(a, &s, &c);
        g_FT[(size_t)col * DMODEL + n] = isIm ? (-s * ORTHO_SCALE) : (c * ORTHO_SCALE);
    } else if (blk < 2056) {
        int idx = (blk - 1028) * 256 + threadIdx.x;
        if (idx >= DMODEL * FCOLS) return;
        int n = idx / FCOLS;
        int j = idx - n * FCOLS;
        int k = j >> 1;
        float a = (float)(k * n) * (1.0f / 256.0f);
        float s, c;
        sincospif(a, &s, &c);
        float val;
        if ((j & 1) == 0) {
            float w = (k == 0 || k == 256) ? 1.0f : 2.0f;
            val = w * c * ORTHO_SCALE;
        } else {
            val = (k == 0 || k == 256) ? 0.0f : (-2.0f * s * ORTHO_SCALE);
        }
        g_G[(size_t)n * FLD + j] = val;
    } else if (blk < 2312) {
        int idx = (blk - 2056) * 256 + threadIdx.x;
        if (idx >= DLOW * DLOW) return;
        int u = idx / DLOW;
        int i = idx - u * DLOW;
        const float* cp = coeffs + ((size_t)u * DLOW + i) * 3;
        g_Wt[(size_t)u * 512 + i]        = cp[1];
        g_Wt[(size_t)u * 512 + 256 + i]  = cp[2];
    } else {
        int u = (blk - 2312) * 8 + (threadIdx.x >> 5);
        int t = threadIdx.x & 31;
        if (u >= DLOW) return;
        float acc = 0.0f;
        const float* cp = coeffs + (size_t)u * DLOW * 3;
        for (int i = t; i < DLOW; i += 32) acc += cp[i * 3];
#pragma unroll
        for (int o = 16; o > 0; o >>= 1) acc += __shfl_xor_sync(0xffffffffu, acc, o);
        if (t == 0) g_bias_t[u] = acc + tb[u];
    }
}

// ---------------- bf16x2-split tensor-core NT GEMM ----------------
// C[m,n] = sum_k A[m,k]*B[n,k].  BM=128, BN=128, BK=16, 128 threads, 4 warps
// (2Mx2N, warp tile 64x64), mma.m16n8k16.bf16, 2-term split (hihi+hilo+lohi).
// Smem: [k2][col] uint2 = (bf16x2 hi-pair, bf16x2 lo-pair), XOR swizzle
// col ^ ((k2&3)<<2), strides exactly 128 -> conflict-free LDS.64/STS.64.
// Total smem 32KB, 2 CTA/SM.
// act: 0=none, 1=softplus(+bias), 2=also write [v, v*v] to aux.

__device__ __forceinline__ uint2 split_bf16x2(float e, float o) {
    uint32_t hi;
    // hi = { bf16(o) : upper16, bf16(e) : lower16 }
    asm("cvt.rn.bf16x2.f32 %0, %1, %2;" : "=r"(hi) : "f"(o), "f"(e));
    float eh = __uint_as_float(hi << 16);
    float oh = __uint_as_float(hi & 0xFFFF0000u);
    uint32_t lo;
    asm("cvt.rn.bf16x2.f32 %0, %1, %2;" : "=r"(lo) : "f"(o - oh), "f"(e - eh));
    return make_uint2(hi, lo);
}

#define MMA_BF16(D, A0, A1, A2, A3, B0, B1)                                  \
    asm volatile("mma.sync.aligned.m16n8k16.row.col.f32.bf16.bf16.f32 "      \
                 "{%0,%1,%2,%3}, {%4,%5,%6,%7}, {%8,%9}, {%0,%1,%2,%3};"     \
                 : "+f"(D[0]), "+f"(D[1]), "+f"(D[2]), "+f"(D[3])            \
                 : "r"(A0), "r"(A1), "r"(A2), "r"(A3), "r"(B0), "r"(B1))

__global__ void __launch_bounds__(128, 2)
tgemm_nt(const float* __restrict__ A, int lda,
         const float* __restrict__ B, int ldb,
         float* __restrict__ C, int ldc,
         int N, int K,
         const float* __restrict__ bias, int act,
         float* __restrict__ aux)
{
    __shared__ uint2 As[2][8][128];   // 16 KB : [k2][m] (hi-pair, lo-pair)
    __shared__ uint2 Bs[2][8][128];   // 16 KB : [k2][n]

    const int tid = threadIdx.x;
    const int m0 = blockIdx.y * 128;
    const int n0 = blockIdx.x * 128;

    // loaders: thread t owns A row m0+t and B row n0+t, 16 k-values each
    const float* Arow = A + (size_t)(m0 + tid) * lda;
    const float* Brow = B + (size_t)(n0 + tid) * ldb;
    const bool bval = (n0 + tid) < N;

    const int wid  = tid >> 5;
    const int lane = tid & 31;
    const int wm = (wid & 1) * 64;     // warp row offset
    const int wn = (wid >> 1) * 64;    // warp col offset
    const int grp = lane >> 2;         // 0..7
    const int qid = lane & 3;
    const int sw  = qid << 2;          // fragment-load swizzle

    float acc[4][8][4];
#pragma unroll
    for (int i = 0; i < 4; i++)
#pragma unroll
        for (int j = 0; j < 8; j++)
#pragma unroll
            for (int r = 0; r < 4; r++) acc[i][j][r] = 0.0f;

    const int ntiles = (K + 15) >> 4;
    float a_reg[16];
    float b_reg[16];

#define LOAD_TILE(t)                                                          \
    {                                                                         \
        int k0 = (t) * 16;                                                    \
        if (k0 + 16 <= K) {                                                   \
            float4 v0 = *reinterpret_cast<const float4*>(Arow + k0);          \
            float4 v1 = *reinterpret_cast<const float4*>(Arow + k0 + 4);      \
            float4 v2 = *reinterpret_cast<const float4*>(Arow + k0 + 8);      \
            float4 v3 = *reinterpret_cast<const float4*>(Arow + k0 + 12);     \
            a_reg[0]=v0.x; a_reg[1]=v0.y; a_reg[2]=v0.z; a_reg[3]=v0.w;       \
            a_reg[4]=v1.x; a_reg[5]=v1.y; a_reg[6]=v1.z; a_reg[7]=v1.w;       \
            a_reg[8]=v2.x; a_reg[9]=v2.y; a_reg[10]=v2.z; a_reg[11]=v2.w;     \
            a_reg[12]=v3.x; a_reg[13]=v3.y; a_reg[14]=v3.z; a_reg[15]=v3.w;   \
            if (bval) {                                                       \
                _Pragma("unroll")                                             \
                for (int c = 0; c < 16; c++) b_reg[c] = Brow[k0 + c];         \
            } else {                                                          \
                _Pragma("unroll")                                             \
                for (int c = 0; c < 16; c++) b_reg[c] = 0.0f;                 \
            }                                                                 \
        } else {                                                              \
            _Pragma("unroll")                                                 \
            for (int c = 0; c < 16; c++) {                                    \
                int kk = k0 + c;                                              \
                a_reg[c] = (kk < K) ? Arow[kk] : 0.0f;                        \
                b_reg[c] = (bval && kk < K) ? Brow[kk] : 0.0f;                \
            }                                                                 \
        }                                                                     \
    }

#define STORE_TILE(buf)                                                       \
    {                                                                         \
        _Pragma("unroll")                                                     \
        for (int c2 = 0; c2 < 8; c2++) {                                      \
            As[buf][c2][tid ^ ((c2 & 3) << 2)] =                              \
                split_bf16x2(a_reg[2 * c2], a_reg[2 * c2 + 1]);               \
            Bs[buf][c2][tid ^ ((c2 & 3) << 2)] =                              \
                split_bf16x2(b_reg[2 * c2], b_reg[2 * c2 + 1]);               \
        }                                                                     \
    }

    LOAD_TILE(0);
    STORE_TILE(0);
    __syncthreads();

    int cur = 0;
    for (int t = 0; t < ntiles; t++) {
        if (t + 1 < ntiles) LOAD_TILE(t + 1);

        // ---- compute on buffer cur: LDS.64 + MMA only ----
        uint2 bf[8][2];
#pragma unroll
        for (int j = 0; j < 8; j++) {
            bf[j][0] = Bs[cur][qid][(wn + j * 8 + grp) ^ sw];
            bf[j][1] = Bs[cur][qid + 4][(wn + j * 8 + grp) ^ sw];
        }
#pragma unroll
        for (int i = 0; i < 4; i++) {
            uint2 a0 = As[cur][qid][(wm + i * 16 + grp) ^ sw];
            uint2 a1 = As[cur][qid][(wm + i * 16 + grp + 8) ^ sw];
            uint2 a2 = As[cur][qid + 4][(wm + i * 16 + grp) ^ sw];
            uint2 a3 = As[cur][qid + 4][(wm + i * 16 + grp + 8) ^ sw];
#pragma unroll
            for (int j = 0; j < 8; j++) {
                MMA_BF16(acc[i][j], a0.x, a1.x, a2.x, a3.x, bf[j][0].x, bf[j][1].x);
                MMA_BF16(acc[i][j], a0.x, a1.x, a2.x, a3.x, bf[j][0].y, bf[j][1].y);
                MMA_BF16(acc[i][j], a0.y, a1.y, a2.y, a3.y, bf[j][0].x, bf[j][1].x);
            }
        }

        if (t + 1 < ntiles) {
            STORE_TILE(cur ^ 1);
            __syncthreads();
            cur ^= 1;
        }
    }

    // ---- epilogue ----
#pragma unroll
    for (int i = 0; i < 4; i++) {
#pragma unroll
        for (int j = 0; j < 8; j++) {
            int r0 = m0 + wm + i * 16 + grp;
            int c0 = n0 + wn + j * 8 + qid * 2;
            float v[4] = {acc[i][j][0], acc[i][j][1], acc[i][j][2], acc[i][j][3]};
#pragma unroll
            for (int e = 0; e < 4; e++) {
                int n = c0 + (e & 1);
                int r = r0 + (e >> 1) * 8;
                if (n < N) {
                    float x = v[e];
                    if (bias) x += bias[n];
                    if (act == 1) x = fmaxf(x, 0.0f) + log1pf(__expf(-fabsf(x)));
                    C[(size_t)r * ldc + n] = x;
                    if (act == 2 && n < DLOW) {
                        aux[(size_t)r * 512 + n]        = x;
                        aux[(size_t)r * 512 + 256 + n]  = x * x;
                    }
                }
            }
        }
    }
}

// ---------------- depthwise causal conv(4) + silu ----------------
__global__ void k_conv_silu(const float* __restrict__ conv_w,
                            const float* __restrict__ conv_b) {
    int idx = blockIdx.x * blockDim.x + threadIdx.x;   // MTOT*DINNER
    if (idx >= MTOT * DINNER) return;
    int m = idx / DINNER;
    int d = idx - m * DINNER;
    int l = m & (LSEQ - 1);
    const float* w = conv_w + d * 4;
    float acc = conv_b[d];
#pragma unroll
    for (int j = 0; j < 4; j++) {
        int ls = l - 3 + j;
        if (ls >= 0) acc += g_xz[(size_t)(m - 3 + j) * 1032 + d] * w[j];
    }
    float sg = 1.0f / (1.0f + __expf(-acc));
    g_xm[(size_t)m * DINNER + d] = acc * sg;
}

// ---------------- selective scan (thread per (b,d,s), 16-lane reduce) ----------
__global__ void k_scan(const float* __restrict__ A_log,
                       const float* __restrict__ D_param) {
    int g = blockIdx.x * 8 + (threadIdx.x >> 4);
    int s = threadIdx.x & 15;
    if (g >= NB * DINNER) return;
    int b = g / DINNER;
    int d = g - b * DINNER;

    const float A  = -__expf(A_log[d * DSTATE + s]);
    const float Dv = D_param[d];

    const size_t rowb = (size_t)b * LSEQ;
    const float* dtp = g_dt   + rowb * DINNER + d;
    const float* xp  = g_xm   + rowb * DINNER + d;
    const float* Bp  = g_xdbl + rowb * XDLD + DTRANK + s;
    const float* Cp  = g_xdbl + rowb * XDLD + DTRANK + DSTATE + s;
    const float* zp  = g_xz   + rowb * 1032 + DINNER + d;
    float*       yp  = g_ys   + rowb * DINNER + d;

    float h = 0.0f;
    for (int t = 0; t < LSEQ; t++) {
        float dtv = dtp[(size_t)t * DINNER];
        float xv  = xp [(size_t)t * DINNER];
        float Bv  = Bp [(size_t)t * XDLD];
        float Cv  = Cp [(size_t)t * XDLD];
        h = __expf(dtv * A) * h + (dtv * xv) * Bv;
        float p = h * Cv;
        p += __shfl_xor_sync(0xffffffffu, p, 1);
        p += __shfl_xor_sync(0xffffffffu, p, 2);
        p += __shfl_xor_sync(0xffffffffu, p, 4);
        p += __shfl_xor_sync(0xffffffffu, p, 8);
        if (s == 0) {
            float zv = zp[(size_t)t * 1032];
            float sg = 1.0f / (1.0f + __expf(-zv));
            yp[(size_t)t * DINNER] = (p + xv * Dv) * (zv * sg);
        }
    }
}

// ---------------- RMSNorm * w + residual ----------------
__global__ void k_norm(const float* __restrict__ x,
                       const float* __restrict__ nw,
                       float* __restrict__ out) {
    int m = blockIdx.x;
    const float* yr = g_ymid + (size_t)m * DMODEL;
    float v[4];
    float ss = 0.0f;
#pragma unroll
    for (int i = 0; i < 4; i++) {
        v[i] = yr[threadIdx.x + i * 128];
        ss += v[i] * v[i];
    }
    __shared__ float red[4];
#pragma unroll
    for (int o = 16; o > 0; o >>= 1) ss += __shfl_xor_sync(0xffffffffu, ss, o);
    if ((threadIdx.x & 31) == 0) red[threadIdx.x >> 5] = ss;
    __syncthreads();
    float tot = red[0] + red[1] + red[2] + red[3];
    float rs = rsqrtf(tot * (1.0f / DMODEL) + 1e-5f);
#pragma unroll
    for (int i = 0; i < 4; i++) {
        int n = threadIdx.x + i * 128;
        out[(size_t)m * DMODEL + n] = v[i] * rs * nw[n] + x[(size_t)m * DMODEL + n];
    }
}

// ---------------- launch ----------------
static inline dim3 tg_grid(int N) { return dim3((N + 127) / 128, MTOT / 128); }

extern "C" void kernel_launch(void* const* d_in, const int* in_sizes, int n_in,
                              void* d_out, int out_size) {
    const float* x             = (const float*)d_in[0];
    const float* taylor_coeffs = (const float*)d_in[1];
    const float* taylor_bias   = (const float*)d_in[2];
    const float* in_proj_w     = (const float*)d_in[3];
    const float* conv_w        = (const float*)d_in[4];
    const float* conv_b        = (const float*)d_in[5];
    const float* x_proj_w      = (const float*)d_in[6];
    const float* dt_proj_w     = (const float*)d_in[7];
    const float* dt_proj_b     = (const float*)d_in[8];
    const float* A_log         = (const float*)d_in[9];
    const float* D_param       = (const float*)d_in[10];
    const float* out_proj_w    = (const float*)d_in[11];
    const float* norm_w        = (const float*)d_in[12];
    float* out = (float*)d_out;

    float *p_FT, *p_G, *p_Wt, *p_bias, *p_xfcat, *p_feat, *p_xz, *p_xm,
          *p_xdbl, *p_dt, *p_ys, *p_ycat, *p_ymid;
    cudaGetSymbolAddress((void**)&p_FT,    g_FT);
    cudaGetSymbolAddress((void**)&p_G,     g_G);
    cudaGetSymbolAddress((void**)&p_Wt,    g_Wt);
    cudaGetSymbolAddress((void**)&p_bias,  g_bias_t);
    cudaGetSymbolAddress((void**)&p_xfcat, g_xfcat);
    cudaGetSymbolAddress((void**)&p_feat,  g_feat);
    cudaGetSymbolAddress((void**)&p_xz,    g_xz);
    cudaGetSymbolAddress((void**)&p_xm,    g_xm);
    cudaGetSymbolAddress((void**)&p_xdbl,  g_xdbl);
    cudaGetSymbolAddress((void**)&p_dt,    g_dt);
    cudaGetSymbolAddress((void**)&p_ys,    g_ys);
    cudaGetSymbolAddress((void**)&p_ycat,  g_ycat);
    cudaGetSymbolAddress((void**)&p_ymid,  g_ymid);

    // 1) fused weight prep
    k_prep<<<2344, 256>>>(taylor_coeffs, taylor_bias);

    // 2) forward DFT (+ fused taylor-feature build): xfcat = x @ FT^T
    tgemm_nt<<<tg_grid(FCOLS), 128>>>(x, DMODEL, p_FT, DMODEL,
                                      p_xfcat, FLD, FCOLS, DMODEL, nullptr, 2, p_feat);
    // 3) taylor GEMM -> ycat[:, 0:256]
    tgemm_nt<<<tg_grid(DLOW), 128>>>(p_feat, 512, p_Wt, 512,
                                     p_ycat, FLD, DLOW, 512, p_bias, 0, nullptr);
    // 4) mamba in_proj: xz = xh_cat @ in_proj_w^T  (M,1032)
    tgemm_nt<<<tg_grid(1032), 128>>>(p_xfcat + 256, FLD, in_proj_w, DMH,
                                     p_xz, 1032, 1032, DMH, nullptr, 0, nullptr);
    // 5) conv + silu -> xm
    k_conv_silu<<<(MTOT * DINNER + 255) / 256, 256>>>(conv_w, conv_b);
    // 6) x_proj: xdbl = xm @ x_proj_w^T  (M,49), ldc=52
    tgemm_nt<<<tg_grid(XDBL_C), 128>>>(p_xm, DINNER, x_proj_w, DINNER,
                                       p_xdbl, XDLD, XDBL_C, DINNER, nullptr, 0, nullptr);
    // 7) dt: softplus(xdbl[:, :17] @ dt_proj_w^T + b)  (M,516)
    tgemm_nt<<<tg_grid(DINNER), 128>>>(p_xdbl, XDLD, dt_proj_w, DTRANK,
                                       p_dt, DINNER, DINNER, DTRANK, dt_proj_b, 1, nullptr);
    // 8) selective scan (fused +x*D and silu(z) gate) -> ys
    k_scan<<<(NB * DINNER + 7) / 8, 128>>>(A_log, D_param);
    // 9) out_proj -> ycat[:, 256:514]
    tgemm_nt<<<tg_grid(DMH), 128>>>(p_ys, DINNER, out_proj_w, DINNER,
                                    p_ycat + 256, FLD, DMH, DINNER, nullptr, 0, nullptr);
    // 10) inverse DFT: ymid = ycat @ G^T  (M,512)
    tgemm_nt<<<tg_grid(DMODEL), 128>>>(p_ycat, FLD, p_G, FLD,
                                       p_ymid, DMODEL, DMODEL, FCOLS, nullptr, 0, nullptr);
    // 11) RMSNorm + residual
    k_norm<<<MTOT, 128>>>(x, norm_w, out);
}

// round 11
// speedup vs baseline: 1.3463x; 1.1301x over previous
#include <cuda_runtime.h>
#include <math.h>
#include <stdint.h>

// ---------------- problem dims ----------------
#define MTOT   16384      // B*L = 16*1024
#define DMODEL 512
#define DLOW   256
#define DMH    258
#define DINNER 516
#define DSTATE 16
#define DTRANK 17
#define XDBL_C 49         // DTRANK + 2*DSTATE
#define FCOLS  514        // 2*257 packed freq channels
#define FLD    516        // padded leading dim for FCOLS buffers
#define XDLD   52         // padded leading dim for xdbl
#define LSEQ   1024
#define NB     16

// ---------------- scratch (device globals; no allocation allowed) ----------------
__device__ float g_FT[FCOLS * DMODEL];
__device__ float g_G [DMODEL * FLD];
__device__ float g_Wt[DLOW * 512];
__device__ float g_bias_t[DLOW];
__device__ float g_xfcat[(size_t)MTOT * FLD + 64];
__device__ float g_feat [(size_t)MTOT * 512 + 64];
__device__ float g_xz   [(size_t)MTOT * 1032 + 64];
__device__ float g_xm   [(size_t)MTOT * DINNER + 64];
__device__ float g_xdbl [(size_t)MTOT * XDLD + 64];
__device__ float g_dt   [(size_t)MTOT * DINNER + 64];
__device__ float g_ys   [(size_t)MTOT * DINNER + 64];
__device__ float g_ycat [(size_t)MTOT * FLD + 64];
__device__ float g_ymid [(size_t)MTOT * DMODEL + 64];

#define ORTHO_SCALE 0.04419417382415922f

// ---------------- fused weight prep (one launch) ----------------
__global__ void k_prep(const float* __restrict__ coeffs,
                       const float* __restrict__ tb) {
    int blk = blockIdx.x;
    if (blk < 1028) {
        int idx = blk * 256 + threadIdx.x;
        if (idx >= FCOLS * DMODEL) return;
        int col = idx / DMODEL;
        int n   = idx - col * DMODEL;
        int k, isIm;
        if (col < 128)      { k = col;             isIm = 0; }
        else if (col < 256) { k = col - 128;       isIm = 1; }
        else if (col < 385) { k = col - 256 + 128; isIm = 0; }
        else                { k = col - 385 + 128; isIm = 1; }
        float a = (float)(k * n) * (1.0f / 256.0f);
        float s, c;
        sincospif(a, &s, &c);
        g_FT[(size_t)col * DMODEL + n] = isIm ? (-s * ORTHO_SCALE) : (c * ORTHO_SCALE);
    } else if (blk < 2056) {
        int idx = (blk - 1028) * 256 + threadIdx.x;
        if (idx >= DMODEL * FCOLS) return;
        int n = idx / FCOLS;
        int j = idx - n * FCOLS;
        int k = j >> 1;
        float a = (float)(k * n) * (1.0f / 256.0f);
        float s, c;
        sincospif(a, &s, &c);
        float val;
        if ((j & 1) == 0) {
            float w = (k == 0 || k == 256) ? 1.0f : 2.0f;
            val = w * c * ORTHO_SCALE;
        } else {
            val = (k == 0 || k == 256) ? 0.0f : (-2.0f * s * ORTHO_SCALE);
        }
        g_G[(size_t)n * FLD + j] = val;
    } else if (blk < 2312) {
        int idx = (blk - 2056) * 256 + threadIdx.x;
        if (idx >= DLOW * DLOW) return;
        int u = idx / DLOW;
        int i = idx - u * DLOW;
        const float* cp = coeffs + ((size_t)u * DLOW + i) * 3;
        g_Wt[(size_t)u * 512 + i]        = cp[1];
        g_Wt[(size_t)u * 512 + 256 + i]  = cp[2];
    } else {
        int u = (blk - 2312) * 8 + (threadIdx.x >> 5);
        int t = threadIdx.x & 31;
        if (u >= DLOW) return;
        float acc = 0.0f;
        const float* cp = coeffs + (size_t)u * DLOW * 3;
        for (int i = t; i < DLOW; i += 32) acc += cp[i * 3];
#pragma unroll
        for (int o = 16; o > 0; o >>= 1) acc += __shfl_xor_sync(0xffffffffu, acc, o);
        if (t == 0) g_bias_t[u] = acc + tb[u];
    }
}

// ---------------- bf16x2-split tensor-core NT GEMM ----------------
// C[m,n] = sum_k A[m,k]*B[n,k].  BM=128, BN=128, BK=16, 256 threads, 8 warps
// (2Mx4N, warp tile 64x32), mma.m16n8k16.bf16, 2-term split (hihi+hilo+lohi).
// Smem: [k2][col] uint2 = (bf16x2 hi-pair, bf16x2 lo-pair), XOR swizzle
// col ^ ((k2&3)<<2), stride 128 -> conflict-free LDS.64/STS.64. 32KB smem.
// act: 0=none, 1=softplus(+bias), 2=also write [v, v*v] to aux.

__device__ __forceinline__ uint2 split_bf16x2(float e, float o) {
    uint32_t hi;
    asm("cvt.rn.bf16x2.f32 %0, %1, %2;" : "=r"(hi) : "f"(o), "f"(e));
    float eh = __uint_as_float(hi << 16);
    float oh = __uint_as_float(hi & 0xFFFF0000u);
    uint32_t lo;
    asm("cvt.rn.bf16x2.f32 %0, %1, %2;" : "=r"(lo) : "f"(o - oh), "f"(e - eh));
    return make_uint2(hi, lo);
}

#define MMA_BF16(D, A0, A1, A2, A3, B0, B1)                                  \
    asm volatile("mma.sync.aligned.m16n8k16.row.col.f32.bf16.bf16.f32 "      \
                 "{%0,%1,%2,%3}, {%4,%5,%6,%7}, {%8,%9}, {%0,%1,%2,%3};"     \
                 : "+f"(D[0]), "+f"(D[1]), "+f"(D[2]), "+f"(D[3])            \
                 : "r"(A0), "r"(A1), "r"(A2), "r"(A3), "r"(B0), "r"(B1))

__global__ void __launch_bounds__(256)
tgemm_nt(const float* __restrict__ A, int lda,
         const float* __restrict__ B, int ldb,
         float* __restrict__ C, int ldc,
         int N, int K,
         const float* __restrict__ bias, int act,
         float* __restrict__ aux)
{
    __shared__ uint2 As[2][8][128];   // 16 KB : [k2][m]
    __shared__ uint2 Bs[2][8][128];   // 16 KB : [k2][n]

    const int tid = threadIdx.x;
    const int m0 = blockIdx.y * 128;
    const int n0 = blockIdx.x * 128;

    // loaders: thread -> row lr (0..127), k-offset lkc (0 or 8)
    const int lr  = tid >> 1;
    const int lkc = (tid & 1) * 8;
    const int lk2 = (tid & 1) * 4;
    const float* Arow = A + (size_t)(m0 + lr) * lda;
    const float* Brow = B + (size_t)(n0 + lr) * ldb;
    const bool bval = (n0 + lr) < N;

    const int wid  = tid >> 5;
    const int lane = tid & 31;
    const int wm = (wid & 1) * 64;     // warp row offset (2 M-warps)
    const int wn = (wid >> 1) * 32;    // warp col offset (4 N-warps)
    const int grp = lane >> 2;         // 0..7
    const int qid = lane & 3;
    const int sw  = qid << 2;          // fragment-load swizzle

    float acc[4][4][4];
#pragma unroll
    for (int i = 0; i < 4; i++)
#pragma unroll
        for (int j = 0; j < 4; j++)
#pragma unroll
            for (int r = 0; r < 4; r++) acc[i][j][r] = 0.0f;

    const int ntiles = (K + 15) >> 4;
    float a_reg[8];
    float b_reg[8];

#define LOAD_TILE(t)                                                          \
    {                                                                         \
        int k0 = (t) * 16 + lkc;                                              \
        if (k0 + 8 <= K) {                                                    \
            float4 v0 = *reinterpret_cast<const float4*>(Arow + k0);          \
            float4 v1 = *reinterpret_cast<const float4*>(Arow + k0 + 4);      \
            a_reg[0]=v0.x; a_reg[1]=v0.y; a_reg[2]=v0.z; a_reg[3]=v0.w;       \
            a_reg[4]=v1.x; a_reg[5]=v1.y; a_reg[6]=v1.z; a_reg[7]=v1.w;       \
            if (bval) {                                                       \
                _Pragma("unroll")                                             \
                for (int c = 0; c < 8; c++) b_reg[c] = Brow[k0 + c];          \
            } else {                                                          \
                _Pragma("unroll")                                             \
                for (int c = 0; c < 8; c++) b_reg[c] = 0.0f;                  \
            }                                                                 \
        } else {                                                              \
            _Pragma("unroll")                                                 \
            for (int c = 0; c < 8; c++) {                                     \
                int kk = k0 + c;                                              \
                a_reg[c] = (kk < K) ? Arow[kk] : 0.0f;                        \
                b_reg[c] = (bval && kk < K) ? Brow[kk] : 0.0f;                \
            }                                                                 \
        }                                                                     \
    }

#define STORE_TILE(buf)                                                       \
    {                                                                         \
        _Pragma("unroll")                                                     \
        for (int c2 = 0; c2 < 4; c2++) {                                      \
            int k2 = lk2 + c2;                                                \
            int col = lr ^ ((k2 & 3) << 2);                                   \
            As[buf][k2][col] = split_bf16x2(a_reg[2 * c2], a_reg[2 * c2 + 1]);\
            Bs[buf][k2][col] = split_bf16x2(b_reg[2 * c2], b_reg[2 * c2 + 1]);\
        }                                                                     \
    }

    LOAD_TILE(0);
    STORE_TILE(0);
    __syncthreads();

    int cur = 0;
    for (int t = 0; t < ntiles; t++) {
        if (t + 1 < ntiles) LOAD_TILE(t + 1);

        // ---- compute on buffer cur: LDS.64 + MMA only ----
        uint2 bf[4][2];
#pragma unroll
        for (int j = 0; j < 4; j++) {
            bf[j][0] = Bs[cur][qid][(wn + j * 8 + grp) ^ sw];
            bf[j][1] = Bs[cur][qid + 4][(wn + j * 8 + grp) ^ sw];
        }
#pragma unroll
        for (int i = 0; i < 4; i++) {
            uint2 a0 = As[cur][qid][(wm + i * 16 + grp) ^ sw];
            uint2 a1 = As[cur][qid][(wm + i * 16 + grp + 8) ^ sw];
            uint2 a2 = As[cur][qid + 4][(wm + i * 16 + grp) ^ sw];
            uint2 a3 = As[cur][qid + 4][(wm + i * 16 + grp + 8) ^ sw];
#pragma unroll
            for (int j = 0; j < 4; j++) {
                MMA_BF16(acc[i][j], a0.x, a1.x, a2.x, a3.x, bf[j][0].x, bf[j][1].x);
                MMA_BF16(acc[i][j], a0.x, a1.x, a2.x, a3.x, bf[j][0].y, bf[j][1].y);
                MMA_BF16(acc[i][j], a0.y, a1.y, a2.y, a3.y, bf[j][0].x, bf[j][1].x);
            }
        }

        if (t + 1 < ntiles) {
            STORE_TILE(cur ^ 1);
            __syncthreads();
            cur ^= 1;
        }
    }

    // ---- epilogue ----
#pragma unroll
    for (int i = 0; i < 4; i++) {
#pragma unroll
        for (int j = 0; j < 4; j++) {
            int r0 = m0 + wm + i * 16 + grp;
            int c0 = n0 + wn + j * 8 + qid * 2;
            float v[4] = {acc[i][j][0], acc[i][j][1], acc[i][j][2], acc[i][j][3]};
#pragma unroll
            for (int e = 0; e < 4; e++) {
                int n = c0 + (e & 1);
                int r = r0 + (e >> 1) * 8;
                if (n < N) {
                    float x = v[e];
                    if (bias) x += bias[n];
                    if (act == 1) x = fmaxf(x, 0.0f) + log1pf(__expf(-fabsf(x)));
                    C[(size_t)r * ldc + n] = x;
                    if (act == 2 && n < DLOW) {
                        aux[(size_t)r * 512 + n]        = x;
                        aux[(size_t)r * 512 + 256 + n]  = x * x;
                    }
                }
            }
        }
    }
}

// ---------------- depthwise causal conv(4) + silu ----------------
__global__ void k_conv_silu(const float* __restrict__ conv_w,
                            const float* __restrict__ conv_b) {
    int idx = blockIdx.x * blockDim.x + threadIdx.x;
    if (idx >= MTOT * DINNER) return;
    int m = idx / DINNER;
    int d = idx - m * DINNER;
    int l = m & (LSEQ - 1);
    const float* w = conv_w + d * 4;
    float acc = conv_b[d];
#pragma unroll
    for (int j = 0; j < 4; j++) {
        int ls = l - 3 + j;
        if (ls >= 0) acc += g_xz[(size_t)(m - 3 + j) * 1032 + d] * w[j];
    }
    float sg = 1.0f / (1.0f + __expf(-acc));
    g_xm[(size_t)m * DINNER + d] = acc * sg;
}

// ---------------- selective scan ----------------
__global__ void k_scan(const float* __restrict__ A_log,
                       const float* __restrict__ D_param) {
    int g = blockIdx.x * 8 + (threadIdx.x >> 4);
    int s = threadIdx.x & 15;
    if (g >= NB * DINNER) return;
    int b = g / DINNER;
    int d = g - b * DINNER;

    const float A  = -__expf(A_log[d * DSTATE + s]);
    const float Dv = D_param[d];

    const size_t rowb = (size_t)b * LSEQ;
    const float* dtp = g_dt   + rowb * DINNER + d;
    const float* xp  = g_xm   + rowb * DINNER + d;
    const float* Bp  = g_xdbl + rowb * XDLD + DTRANK + s;
    const float* Cp  = g_xdbl + rowb * XDLD + DTRANK + DSTATE + s;
    const float* zp  = g_xz   + rowb * 1032 + DINNER + d;
    float*       yp  = g_ys   + rowb * DINNER + d;

    float h = 0.0f;
    for (int t = 0; t < LSEQ; t++) {
        float dtv = dtp[(size_t)t * DINNER];
        float xv  = xp [(size_t)t * DINNER];
        float Bv  = Bp [(size_t)t * XDLD];
        float Cv  = Cp [(size_t)t * XDLD];
        h = __expf(dtv * A) * h + (dtv * xv) * Bv;
        float p = h * Cv;
        p += __shfl_xor_sync(0xffffffffu, p, 1);
        p += __shfl_xor_sync(0xffffffffu, p, 2);
        p += __shfl_xor_sync(0xffffffffu, p, 4);
        p += __shfl_xor_sync(0xffffffffu, p, 8);
        if (s == 0) {
            float zv = zp[(size_t)t * 1032];
            float sg = 1.0f / (1.0f + __expf(-zv));
            yp[(size_t)t * DINNER] = (p + xv * Dv) * (zv * sg);
        }
    }
}

// ---------------- RMSNorm * w + residual ----------------
__global__ void k_norm(const float* __restrict__ x,
                       const float* __restrict__ nw,
                       float* __restrict__ out) {
    int m = blockIdx.x;
    const float* yr = g_ymid + (size_t)m * DMODEL;
    float v[4];
    float ss = 0.0f;
#pragma unroll
    for (int i = 0; i < 4; i++) {
        v[i] = yr[threadIdx.x + i * 128];
        ss += v[i] * v[i];
    }
    __shared__ float red[4];
#pragma unroll
    for (int o = 16; o > 0; o >>= 1) ss += __shfl_xor_sync(0xffffffffu, ss, o);
    if ((threadIdx.x & 31) == 0) red[threadIdx.x >> 5] = ss;
    __syncthreads();
    float tot = red[0] + red[1] + red[2] + red[3];
    float rs = rsqrtf(tot * (1.0f / DMODEL) + 1e-5f);
#pragma unroll
    for (int i = 0; i < 4; i++) {
        int n = threadIdx.x + i * 128;
        out[(size_t)m * DMODEL + n] = v[i] * rs * nw[n] + x[(size_t)m * DMODEL + n];
    }
}

// ---------------- launch ----------------
static inline dim3 tg_grid(int N) { return dim3((N + 127) / 128, MTOT / 128); }

extern "C" void kernel_launch(void* const* d_in, const int* in_sizes, int n_in,
                              void* d_out, int out_size) {
    const float* x             = (const float*)d_in[0];
    const float* taylor_coeffs = (const float*)d_in[1];
    const float* taylor_bias   = (const float*)d_in[2];
    const float* in_proj_w     = (const float*)d_in[3];
    const float* conv_w        = (const float*)d_in[4];
    const float* conv_b        = (const float*)d_in[5];
    const float* x_proj_w      = (const float*)d_in[6];
    const float* dt_proj_w     = (const float*)d_in[7];
    const float* dt_proj_b     = (const float*)d_in[8];
    const float* A_log         = (const float*)d_in[9];
    const float* D_param       = (const float*)d_in[10];
    const float* out_proj_w    = (const float*)d_in[11];
    const float* norm_w        = (const float*)d_in[12];
    float* out = (float*)d_out;

    float *p_FT, *p_G, *p_Wt, *p_bias, *p_xfcat, *p_feat, *p_xz, *p_xm,
          *p_xdbl, *p_dt, *p_ys, *p_ycat, *p_ymid;
    cudaGetSymbolAddress((void**)&p_FT,    g_FT);
    cudaGetSymbolAddress((void**)&p_G,     g_G);
    cudaGetSymbolAddress((void**)&p_Wt,    g_Wt);
    cudaGetSymbolAddress((void**)&p_bias,  g_bias_t);
    cudaGetSymbolAddress((void**)&p_xfcat, g_xfcat);
    cudaGetSymbolAddress((void**)&p_feat,  g_feat);
    cudaGetSymbolAddress((void**)&p_xz,    g_xz);
    cudaGetSymbolAddress((void**)&p_xm,    g_xm);
    cudaGetSymbolAddress((void**)&p_xdbl,  g_xdbl);
    cudaGetSymbolAddress((void**)&p_dt,    g_dt);
    cudaGetSymbolAddress((void**)&p_ys,    g_ys);
    cudaGetSymbolAddress((void**)&p_ycat,  g_ycat);
    cudaGetSymbolAddress((void**)&p_ymid,  g_ymid);

    // 1) fused weight prep
    k_prep<<<2344, 256>>>(taylor_coeffs, taylor_bias);

    // 2) forward DFT (+ fused taylor-feature build): xfcat = x @ FT^T
    tgemm_nt<<<tg_grid(FCOLS), 256>>>(x, DMODEL, p_FT, DMODEL,
                                      p_xfcat, FLD, FCOLS, DMODEL, nullptr, 2, p_feat);
    // 3) taylor GEMM -> ycat[:, 0:256]
    tgemm_nt<<<tg_grid(DLOW), 256>>>(p_feat, 512, p_Wt, 512,
                                     p_ycat, FLD, DLOW, 512, p_bias, 0, nullptr);
    // 4) mamba in_proj: xz = xh_cat @ in_proj_w^T  (M,1032)
    tgemm_nt<<<tg_grid(1032), 256>>>(p_xfcat + 256, FLD, in_proj_w, DMH,
                                     p_xz, 1032, 1032, DMH, nullptr, 0, nullptr);
    // 5) conv + silu -> xm
    k_conv_silu<<<(MTOT * DINNER + 255) / 256, 256>>>(conv_w, conv_b);
    // 6) x_proj: xdbl = xm @ x_proj_w^T  (M,49)
    tgemm_nt<<<tg_grid(XDBL_C), 256>>>(p_xm, DINNER, x_proj_w, DINNER,
                                       p_xdbl, XDLD, XDBL_C, DINNER, nullptr, 0, nullptr);
    // 7) dt: softplus(xdbl[:, :17] @ dt_proj_w^T + b)  (M,516)
    tgemm_nt<<<tg_grid(DINNER), 256>>>(p_xdbl, XDLD, dt_proj_w, DTRANK,
                                       p_dt, DINNER, DINNER, DTRANK, dt_proj_b, 1, nullptr);
    // 8) selective scan
    k_scan<<<(NB * DINNER + 7) / 8, 128>>>(A_log, D_param);
    // 9) out_proj -> ycat[:, 256:514]
    tgemm_nt<<<tg_grid(DMH), 256>>>(p_ys, DINNER, out_proj_w, DINNER,
                                    p_ycat + 256, FLD, DMH, DINNER, nullptr, 0, nullptr);
    // 10) inverse DFT: ymid = ycat @ G^T  (M,512)
    tgemm_nt<<<tg_grid(DMODEL), 256>>>(p_ycat, FLD, p_G, FLD,
                                       p_ymid, DMODEL, DMODEL, FCOLS, nullptr, 0, nullptr);
    // 11) RMSNorm + residual
    k_norm<<<MTOT, 128>>>(x, norm_w, out);
}

// round 12
// speedup vs baseline: 1.3846x; 1.0284x over previous
#include <cuda_runtime.h>
#include <math.h>
#include <stdint.h>

// ---------------- problem dims ----------------
#define MTOT   16384      // B*L
#define DMODEL 512
#define DLOW   256
#define DMH    258
#define DINNER 516
#define DSTATE 16
#define DTRANK 17
#define XDBL_C 49
#define FCOLS  514
#define XDLD   52
#define LSEQ   1024
#define NB     16

// split-buffer leading dims (uint2 entries per row; multiples of 8, zero-padded)
#define FT2LD   256   // K=512
#define G2LD    264   // K=514
#define WT2LD   256   // K=512
#define INW2LD  136   // K=258
#define XPW2LD  264   // K=516
#define DTW2LD  16    // K=17
#define OW2LD   264   // K=516
#define XS2LD   256
#define XFH2LD  136
#define FEAT2LD 256
#define XM2LD   264
#define XDBL2LD 16
#define YS2LD   264
#define YCAT2LD 264

// ---------------- scratch (device globals; zero-initialized, no allocation) ----
// uint4-typed for 16B alignment; each uint4 = 2 split entries (entry = hi,lo bf16x2)
__device__ uint4 g_FT2 [640  * FT2LD  / 2];
__device__ uint4 g_G2  [512  * G2LD   / 2];
__device__ uint4 g_Wt2 [256  * WT2LD  / 2];
__device__ uint4 g_inw2[1152 * INW2LD / 2];
__device__ uint4 g_xpw2[128  * XPW2LD / 2];
__device__ uint4 g_dtw2[640  * DTW2LD / 2];
__device__ uint4 g_ow2 [384  * OW2LD  / 2];
__device__ uint4 g_xs2  [(size_t)MTOT * XS2LD  / 2];
__device__ uint4 g_xfh2 [(size_t)MTOT * XFH2LD / 2];
__device__ uint4 g_feat2[(size_t)MTOT * FEAT2LD/ 2];
__device__ uint4 g_xm2  [(size_t)MTOT * XM2LD  / 2];
__device__ uint4 g_xdbl2[(size_t)MTOT * XDBL2LD/ 2];
__device__ uint4 g_ys2  [(size_t)MTOT * YS2LD  / 2];
__device__ uint4 g_ycat2[(size_t)MTOT * YCAT2LD/ 2];
__device__ float g_bias_t[DLOW];
__device__ float g_xz  [(size_t)MTOT * 1032 + 64];
__device__ float g_xm  [(size_t)MTOT * DINNER + 64];
__device__ float g_xdbl[(size_t)MTOT * XDLD + 64];
__device__ float g_dt  [(size_t)MTOT * DINNER + 64];
__device__ float g_ymid[(size_t)MTOT * DMODEL + 64];

#define ORTHO_SCALE 0.04419417382415922f

__device__ __forceinline__ uint2 split_bf16x2(float e, float o) {
    uint32_t hi;
    asm("cvt.rn.bf16x2.f32 %0, %1, %2;" : "=r"(hi) : "f"(o), "f"(e));
    float eh = __uint_as_float(hi << 16);
    float oh = __uint_as_float(hi & 0xFFFF0000u);
    uint32_t lo;
    asm("cvt.rn.bf16x2.f32 %0, %1, %2;" : "=r"(lo) : "f"(o - oh), "f"(e - eh));
    return make_uint2(hi, lo);
}

// ---------------- fused prep: DFT matrices + weight splits + x split -----------
__device__ __forceinline__ float ft_val(int col, int n) {
    int k, isIm;
    if (col < 128)      { k = col;             isIm = 0; }
    else if (col < 256) { k = col - 128;       isIm = 1; }
    else if (col < 385) { k = col - 256 + 128; isIm = 0; }
    else                { k = col - 385 + 128; isIm = 1; }
    float a = (float)(k * n) * (1.0f / 256.0f);
    float s, c;
    sincospif(a, &s, &c);
    return isIm ? (-s * ORTHO_SCALE) : (c * ORTHO_SCALE);
}

__device__ __forceinline__ void wsplit(const float* __restrict__ w, int Kin,
                                       uint2* __restrict__ dst, int ld2,
                                       int idx, int nent) {
    int r = idx / nent;
    int j = idx - r * nent;
    float v0 = w[(size_t)r * Kin + 2 * j];
    float v1 = (2 * j + 1 < Kin) ? w[(size_t)r * Kin + 2 * j + 1] : 0.0f;
    dst[(size_t)r * ld2 + j] = split_bf16x2(v0, v1);
}

// segment block offsets (256 threads per block)
#define PB_FT   514
#define PB_G    1028
#define PB_WT   1284
#define PB_INW  1805
#define PB_XPW  1855
#define PB_DTW  1874
#define PB_OW   2135
#define PB_BIAS 2167
#define PB_XS   18551

__global__ void k_prep(const float* __restrict__ x,
                       const float* __restrict__ coeffs,
                       const float* __restrict__ tb,
                       const float* __restrict__ in_proj_w,
                       const float* __restrict__ x_proj_w,
                       const float* __restrict__ dt_proj_w,
                       const float* __restrict__ out_proj_w) {
    int blk = blockIdx.x;
    if (blk < PB_FT) {
        int idx = blk * 256 + threadIdx.x;           // 514*256
        if (idx >= 514 * 256) return;
        int col = idx >> 8, j = idx & 255;
        reinterpret_cast<uint2*>(g_FT2)[(size_t)col * FT2LD + j] =
            split_bf16x2(ft_val(col, 2 * j), ft_val(col, 2 * j + 1));
    } else if (blk < PB_G) {
        int idx = (blk - PB_FT) * 256 + threadIdx.x; // 512*257
        if (idx >= 512 * 257) return;
        int n = idx / 257, k = idx - n * 257;        // entry k = cols (2k,2k+1) = (Re_k, Im_k)
        float a = (float)(k * n) * (1.0f / 256.0f);
        float s, c;
        sincospif(a, &s, &c);
        float wr = (k == 0 || k == 256) ? 1.0f : 2.0f;
        float v0 = wr * c * ORTHO_SCALE;
        float v1 = (k == 0 || k == 256) ? 0.0f : (-2.0f * s * ORTHO_SCALE);
        reinterpret_cast<uint2*>(g_G2)[(size_t)n * G2LD + k] = split_bf16x2(v0, v1);
    } else if (blk < PB_WT) {
        int idx = (blk - PB_G) * 256 + threadIdx.x;  // 256*256
        int u = idx >> 8, j = idx & 255;
        const float* cp = coeffs + (size_t)u * DLOW * 3;
        float v0, v1;
        if (j < 128) { v0 = cp[(2 * j) * 3 + 1];         v1 = cp[(2 * j + 1) * 3 + 1]; }
        else { int jj = j - 128; v0 = cp[(2 * jj) * 3 + 2]; v1 = cp[(2 * jj + 1) * 3 + 2]; }
        reinterpret_cast<uint2*>(g_Wt2)[(size_t)u * WT2LD + j] = split_bf16x2(v0, v1);
    } else if (blk < PB_INW) {
        int idx = (blk - PB_WT) * 256 + threadIdx.x; // 1032*129
        if (idx >= 1032 * 129) return;
        wsplit(in_proj_w, DMH, reinterpret_cast<uint2*>(g_inw2), INW2LD, idx, 129);
    } else if (blk < PB_XPW) {
        int idx = (blk - PB_INW) * 256 + threadIdx.x; // 49*258
        if (idx >= 49 * 258) return;
        wsplit(x_proj_w, DINNER, reinterpret_cast<uint2*>(g_xpw2), XPW2LD, idx, 258);
    } else if (blk < PB_DTW) {
        int idx = (blk - PB_XPW) * 256 + threadIdx.x; // 516*9
        if (idx >= 516 * 9) return;
        wsplit(dt_proj_w, DTRANK, reinterpret_cast<uint2*>(g_dtw2), DTW2LD, idx, 9);
    } else if (blk < PB_OW) {
        int idx = (blk - PB_DTW) * 256 + threadIdx.x; // 258*258
        if (idx >= 258 * 258) return;
        wsplit(out_proj_w, DINNER, reinterpret_cast<uint2*>(g_ow2), OW2LD, idx, 258);
    } else if (blk < PB_BIAS) {
        int u = (blk - PB_OW) * 8 + (threadIdx.x >> 5);
        int t = threadIdx.x & 31;
        if (u >= DLOW) return;
        float acc = 0.0f;
        const float* cp = coeffs + (size_t)u * DLOW * 3;
        for (int i = t; i < DLOW; i += 32) acc += cp[i * 3];
#pragma unroll
        for (int o = 16; o > 0; o >>= 1) acc += __shfl_xor_sync(0xffffffffu, acc, o);
        if (t == 0) g_bias_t[u] = acc + tb[u];
    } else {
        int idx = (blk - PB_BIAS) * 256 + threadIdx.x; // 16384*256
        int m = idx >> 8, j = idx & 255;
        reinterpret_cast<uint2*>(g_xs2)[(size_t)m * XS2LD + j] =
            split_bf16x2(x[(size_t)m * DMODEL + 2 * j], x[(size_t)m * DMODEL + 2 * j + 1]);
    }
}

// ---------------- bf16x2-split tensor-core NT GEMM (pre-split operands) --------
// CTA 128x128, BK=16, 256 thr, 8 warps (2Mx4N, warp 64x32), m16n8k16 bf16,
// 3-pass split. Operands are pre-split uint2 entries; loader = 4x LDG.128 + STS.
// Epilogue: optional fp32 C (softplus if act==1, bias), optional split output sp
// (entry soff + n/2, clip), act==2 = DFT special (feat2 + xfh2).

#define MMA_BF16(D, A0, A1, A2, A3, B0, B1)                                  \
    asm volatile("mma.sync.aligned.m16n8k16.row.col.f32.bf16.bf16.f32 "      \
                 "{%0,%1,%2,%3}, {%4,%5,%6,%7}, {%8,%9}, {%0,%1,%2,%3};"     \
                 : "+f"(D[0]), "+f"(D[1]), "+f"(D[2]), "+f"(D[3])            \
                 : "r"(A0), "r"(A1), "r"(A2), "r"(A3), "r"(B0), "r"(B1))

__global__ void __launch_bounds__(256)
tgemm2(const uint2* __restrict__ A2, int lda2,
       const uint2* __restrict__ B2, int ldb2,
       float* __restrict__ C, int ldc, int N, int K,
       const float* __restrict__ bias, int act,
       uint2* __restrict__ sp, int sld2, int soff, int clip)
{
    __shared__ uint2 As[2][8][128];
    __shared__ uint2 Bs[2][8][128];

    const int tid = threadIdx.x;
    const int m0 = blockIdx.y * 128;
    const int n0 = blockIdx.x * 128;

    const int lr  = tid >> 1;
    const int lk2 = (tid & 1) * 4;
    const uint2* Arow = A2 + (size_t)(m0 + lr) * lda2;
    const uint2* Brow = B2 + (size_t)(n0 + lr) * ldb2;

    const int wid  = tid >> 5;
    const int lane = tid & 31;
    const int wm = (wid & 1) * 64;
    const int wn = (wid >> 1) * 32;
    const int grp = lane >> 2;
    const int qid = lane & 3;
    const int sw  = qid << 2;

    float acc[4][4][4];
#pragma unroll
    for (int i = 0; i < 4; i++)
#pragma unroll
        for (int j = 0; j < 4; j++)
#pragma unroll
            for (int r = 0; r < 4; r++) acc[i][j][r] = 0.0f;

    const int ntiles = (K + 15) >> 4;
    uint4 a01, a23, b01, b23;

#define LOAD_TILE2(t)                                                         \
    {                                                                         \
        int e0 = (t) * 8 + lk2;                                               \
        a01 = *reinterpret_cast<const uint4*>(Arow + e0);                     \
        a23 = *reinterpret_cast<const uint4*>(Arow + e0 + 2);                 \
        b01 = *reinterpret_cast<const uint4*>(Brow + e0);                     \
        b23 = *reinterpret_cast<const uint4*>(Brow + e0 + 2);                 \
    }
#define STORE_TILE2(buf)                                                      \
    {                                                                         \
        As[buf][lk2 + 0][lr ^ 0]  = make_uint2(a01.x, a01.y);                 \
        As[buf][lk2 + 1][lr ^ 4]  = make_uint2(a01.z, a01.w);                 \
        As[buf][lk2 + 2][lr ^ 8]  = make_uint2(a23.x, a23.y);                 \
        As[buf][lk2 + 3][lr ^ 12] = make_uint2(a23.z, a23.w);                 \
        Bs[buf][lk2 + 0][lr ^ 0]  = make_uint2(b01.x, b01.y);                 \
        Bs[buf][lk2 + 1][lr ^ 4]  = make_uint2(b01.z, b01.w);                 \
        Bs[buf][lk2 + 2][lr ^ 8]  = make_uint2(b23.x, b23.y);                 \
        Bs[buf][lk2 + 3][lr ^ 12] = make_uint2(b23.z, b23.w);                 \
    }

    LOAD_TILE2(0);
    STORE_TILE2(0);
    __syncthreads();

    int cur = 0;
    for (int t = 0; t < ntiles; t++) {
        if (t + 1 < ntiles) LOAD_TILE2(t + 1);

        uint2 bf[4][2];
#pragma unroll
        for (int j = 0; j < 4; j++) {
            bf[j][0] = Bs[cur][qid][(wn + j * 8 + grp) ^ sw];
            bf[j][1] = Bs[cur][qid + 4][(wn + j * 8 + grp) ^ sw];
        }
#pragma unroll
        for (int i = 0; i < 4; i++) {
            uint2 a0 = As[cur][qid][(wm + i * 16 + grp) ^ sw];
            uint2 a1 = As[cur][qid][(wm + i * 16 + grp + 8) ^ sw];
            uint2 a2 = As[cur][qid + 4][(wm + i * 16 + grp) ^ sw];
            uint2 a3 = As[cur][qid + 4][(wm + i * 16 + grp + 8) ^ sw];
#pragma unroll
            for (int j = 0; j < 4; j++) {
                MMA_BF16(acc[i][j], a0.x, a1.x, a2.x, a3.x, bf[j][0].x, bf[j][1].x);
                MMA_BF16(acc[i][j], a0.x, a1.x, a2.x, a3.x, bf[j][0].y, bf[j][1].y);
                MMA_BF16(acc[i][j], a0.y, a1.y, a2.y, a3.y, bf[j][0].x, bf[j][1].x);
            }
        }

        if (t + 1 < ntiles) {
            STORE_TILE2(cur ^ 1);
            __syncthreads();
            cur ^= 1;
        }
    }

    // ---- epilogue ----
#pragma unroll
    for (int i = 0; i < 4; i++) {
#pragma unroll
        for (int j = 0; j < 4; j++) {
            int r0 = m0 + wm + i * 16 + grp;
            int c0 = n0 + wn + j * 8 + qid * 2;
            float v[4] = {acc[i][j][0], acc[i][j][1], acc[i][j][2], acc[i][j][3]};
            if (bias) {
                if (c0 < N)     { float b0 = bias[c0];     v[0] += b0; v[2] += b0; }
                if (c0 + 1 < N) { float b1 = bias[c0 + 1]; v[1] += b1; v[3] += b1; }
            }
            if (act == 1) {
#pragma unroll
                for (int e = 0; e < 4; e++)
                    v[e] = fmaxf(v[e], 0.0f) + log1pf(__expf(-fabsf(v[e])));
            }
            if (C) {
#pragma unroll
                for (int e = 0; e < 4; e++) {
                    int n = c0 + (e & 1);
                    if (n < N)
                        C[(size_t)(r0 + (e >> 1) * 8) * ldc + n] = v[e];
                }
            }
            if (act == 2) {
                uint2* feat2 = reinterpret_cast<uint2*>(g_feat2);
                uint2* xfh2  = reinterpret_cast<uint2*>(g_xfh2);
#pragma unroll
                for (int pe = 0; pe < 4; pe += 2) {
                    int r = r0 + (pe ? 8 : 0);
                    if (c0 < 256) {
                        feat2[(size_t)r * FEAT2LD + (c0 >> 1)] =
                            split_bf16x2(v[pe], v[pe + 1]);
                        feat2[(size_t)r * FEAT2LD + 128 + (c0 >> 1)] =
                            split_bf16x2(v[pe] * v[pe], v[pe + 1] * v[pe + 1]);
                    } else if (c0 < 514) {
                        xfh2[(size_t)r * XFH2LD + ((c0 - 256) >> 1)] =
                            split_bf16x2(v[pe], v[pe + 1]);
                    }
                }
            } else if (sp) {
#pragma unroll
                for (int pe = 0; pe < 4; pe += 2) {
                    int r = r0 + (pe ? 8 : 0);
                    if (c0 < clip && c0 < N) {
                        float v1 = (c0 + 1 < clip && c0 + 1 < N) ? v[pe + 1] : 0.0f;
                        sp[(size_t)r * sld2 + soff + (c0 >> 1)] =
                            split_bf16x2(v[pe], v1);
                    }
                }
            }
        }
    }
}

// ---------------- depthwise causal conv(4) + silu (pair output) ---------------
__global__ void k_conv_silu(const float* __restrict__ conv_w,
                            const float* __restrict__ conv_b) {
    int idx = blockIdx.x * blockDim.x + threadIdx.x;   // MTOT*258
    if (idx >= MTOT * 258) return;
    int m  = idx / 258;
    int d2 = idx - m * 258;
    int l  = m & (LSEQ - 1);
    float y[2];
#pragma unroll
    for (int dd = 0; dd < 2; dd++) {
        int d = 2 * d2 + dd;
        const float* w = conv_w + d * 4;
        float acc = conv_b[d];
#pragma unroll
        for (int j = 0; j < 4; j++) {
            int ls = l - 3 + j;
            if (ls >= 0) acc += g_xz[(size_t)(m - 3 + j) * 1032 + d] * w[j];
        }
        float sg = 1.0f / (1.0f + __expf(-acc));
        y[dd] = acc * sg;
        g_xm[(size_t)m * DINNER + d] = y[dd];
    }
    reinterpret_cast<uint2*>(g_xm2)[(size_t)m * XM2LD + d2] = split_bf16x2(y[0], y[1]);
}

// ---------------- selective scan (split-pair output via shfl) -----------------
__global__ void k_scan(const float* __restrict__ A_log,
                       const float* __restrict__ D_param) {
    int g = blockIdx.x * 8 + (threadIdx.x >> 4);
    int s = threadIdx.x & 15;
    if (g >= NB * DINNER) return;
    int b = g / DINNER;
    int d = g - b * DINNER;

    const float A  = -__expf(A_log[d * DSTATE + s]);
    const float Dv = D_param[d];

    const size_t rowb = (size_t)b * LSEQ;
    const float* dtp = g_dt   + rowb * DINNER + d;
    const float* xp  = g_xm   + rowb * DINNER + d;
    const float* Bp  = g_xdbl + rowb * XDLD + DTRANK + s;
    const float* Cp  = g_xdbl + rowb * XDLD + DTRANK + DSTATE + s;
    const float* zp  = g_xz   + rowb * 1032 + DINNER + d;
    uint2* ys2 = reinterpret_cast<uint2*>(g_ys2);

    float h = 0.0f;
    for (int t = 0; t < LSEQ; t++) {
        float dtv = dtp[(size_t)t * DINNER];
        float xv  = xp [(size_t)t * DINNER];
        float Bv  = Bp [(size_t)t * XDLD];
        float Cv  = Cp [(size_t)t * XDLD];
        h = __expf(dtv * A) * h + (dtv * xv) * Bv;
        float p = h * Cv;
        p += __shfl_xor_sync(0xffffffffu, p, 1);
        p += __shfl_xor_sync(0xffffffffu, p, 2);
        p += __shfl_xor_sync(0xffffffffu, p, 4);
        p += __shfl_xor_sync(0xffffffffu, p, 8);
        float yv = 0.0f;
        if (s == 0) {
            float zv = zp[(size_t)t * 1032];
            float sg = 1.0f / (1.0f + __expf(-zv));
            yv = (p + xv * Dv) * (zv * sg);
        }
        // pair adjacent d (groups are warp-aligned: lanes 0 and 16 are s==0)
        float y1 = __shfl_down_sync(0xffffffffu, yv, 16);
        if ((threadIdx.x & 31) == 0)
            ys2[(rowb + t) * YS2LD + (d >> 1)] = split_bf16x2(yv, y1);
    }
}

// ---------------- RMSNorm * w + residual ----------------
__global__ void k_norm(const float* __restrict__ x,
                       const float* __restrict__ nw,
                       float* __restrict__ out) {
    int m = blockIdx.x;
    const float* yr = g_ymid + (size_t)m * DMODEL;
    float v[4];
    float ss = 0.0f;
#pragma unroll
    for (int i = 0; i < 4; i++) {
        v[i] = yr[threadIdx.x + i * 128];
        ss += v[i] * v[i];
    }
    __shared__ float red[4];
#pragma unroll
    for (int o = 16; o > 0; o >>= 1) ss += __shfl_xor_sync(0xffffffffu, ss, o);
    if ((threadIdx.x & 31) == 0) red[threadIdx.x >> 5] = ss;
    __syncthreads();
    float tot = red[0] + red[1] + red[2] + red[3];
    float rs = rsqrtf(tot * (1.0f / DMODEL) + 1e-5f);
#pragma unroll
    for (int i = 0; i < 4; i++) {
        int n = threadIdx.x + i * 128;
        out[(size_t)m * DMODEL + n] = v[i] * rs * nw[n] + x[(size_t)m * DMODEL + n];
    }
}

// ---------------- launch ----------------
#define BIGCLIP (1 << 30)
static inline dim3 tg_grid(int N) { return dim3((N + 127) / 128, MTOT / 128); }

extern "C" void kernel_launch(void* const* d_in, const int* in_sizes, int n_in,
                              void* d_out, int out_size) {
    const float* x             = (const float*)d_in[0];
    const float* taylor_coeffs = (const float*)d_in[1];
    const float* taylor_bias   = (const float*)d_in[2];
    const float* in_proj_w     = (const float*)d_in[3];
    const float* conv_w        = (const float*)d_in[4];
    const float* conv_b        = (const float*)d_in[5];
    const float* x_proj_w      = (const float*)d_in[6];
    const float* dt_proj_w     = (const float*)d_in[7];
    const float* dt_proj_b     = (const float*)d_in[8];
    const float* A_log         = (const float*)d_in[9];
    const float* D_param       = (const float*)d_in[10];
    const float* out_proj_w    = (const float*)d_in[11];
    const float* norm_w        = (const float*)d_in[12];
    float* out = (float*)d_out;

    void *pFT2, *pG2, *pWt2, *pinw2, *pxpw2, *pdtw2, *pow2,
         *pxs2, *pxfh2, *pfeat2, *pxm2, *pxdbl2, *pys2, *pycat2;
    float *p_bias, *p_xz, *p_xm, *p_xdbl, *p_dt, *p_ymid;
    cudaGetSymbolAddress(&pFT2,   g_FT2);
    cudaGetSymbolAddress(&pG2,    g_G2);
    cudaGetSymbolAddress(&pWt2,   g_Wt2);
    cudaGetSymbolAddress(&pinw2,  g_inw2);
    cudaGetSymbolAddress(&pxpw2,  g_xpw2);
    cudaGetSymbolAddress(&pdtw2,  g_dtw2);
    cudaGetSymbolAddress(&pow2,   g_ow2);
    cudaGetSymbolAddress(&pxs2,   g_xs2);
    cudaGetSymbolAddress(&pxfh2,  g_xfh2);
    cudaGetSymbolAddress(&pfeat2, g_feat2);
    cudaGetSymbolAddress(&pxm2,   g_xm2);
    cudaGetSymbolAddress(&pxdbl2, g_xdbl2);
    cudaGetSymbolAddress(&pys2,   g_ys2);
    cudaGetSymbolAddress(&pycat2, g_ycat2);
    cudaGetSymbolAddress((void**)&p_bias, g_bias_t);
    cudaGetSymbolAddress((void**)&p_xz,   g_xz);
    cudaGetSymbolAddress((void**)&p_xm,   g_xm);
    cudaGetSymbolAddress((void**)&p_xdbl, g_xdbl);
    cudaGetSymbolAddress((void**)&p_dt,   g_dt);
    cudaGetSymbolAddress((void**)&p_ymid, g_ymid);

    // 1) fused prep: DFT matrices + weight splits + x split + taylor bias
    k_prep<<<PB_XS, 256>>>(x, taylor_coeffs, taylor_bias,
                           in_proj_w, x_proj_w, dt_proj_w, out_proj_w);

    // 2) forward DFT (+ fused feat/xfh split outputs): act=2
    tgemm2<<<tg_grid(FCOLS), 256>>>((const uint2*)pxs2, XS2LD,
                                    (const uint2*)pFT2, FT2LD,
                                    nullptr, 0, FCOLS, DMODEL, nullptr, 2,
                                    nullptr, 0, 0, 0);
    // 3) taylor GEMM -> ycat2 entries [0,128)
    tgemm2<<<tg_grid(DLOW), 256>>>((const uint2*)pfeat2, FEAT2LD,
                                   (const uint2*)pWt2, WT2LD,
                                   nullptr, 0, DLOW, 512, p_bias, 0,
                                   (uint2*)pycat2, YCAT2LD, 0, BIGCLIP);
    // 4) in_proj: xz fp32
    tgemm2<<<tg_grid(1032), 256>>>((const uint2*)pxfh2, XFH2LD,
                                   (const uint2*)pinw2, INW2LD,
                                   p_xz, 1032, 1032, DMH, nullptr, 0,
                                   nullptr, 0, 0, 0);
    // 5) conv + silu -> xm fp32 + xm2
    k_conv_silu<<<(MTOT * 258 + 255) / 256, 256>>>(conv_w, conv_b);
    // 6) x_proj: xdbl fp32 + xdbl2 (clip 17)
    tgemm2<<<tg_grid(XDBL_C), 256>>>((const uint2*)pxm2, XM2LD,
                                     (const uint2*)pxpw2, XPW2LD,
                                     p_xdbl, XDLD, XDBL_C, DINNER, nullptr, 0,
                                     (uint2*)pxdbl2, XDBL2LD, 0, DTRANK);
    // 7) dt: softplus(xdbl2 @ dtw2 + b) -> dt fp32
    tgemm2<<<tg_grid(DINNER), 256>>>((const uint2*)pxdbl2, XDBL2LD,
                                     (const uint2*)pdtw2, DTW2LD,
                                     p_dt, DINNER, DINNER, DTRANK, dt_proj_b, 1,
                                     nullptr, 0, 0, 0);
    // 8) selective scan -> ys2
    k_scan<<<(NB * DINNER) / 8, 128>>>(A_log, D_param);
    // 9) out_proj -> ycat2 entries [128,257)
    tgemm2<<<tg_grid(DMH), 256>>>((const uint2*)pys2, YS2LD,
                                  (const uint2*)pow2, OW2LD,
                                  nullptr, 0, DMH, DINNER, nullptr, 0,
                                  (uint2*)pycat2, YCAT2LD, 128, BIGCLIP);
    // 10) inverse DFT -> ymid fp32
    tgemm2<<<tg_grid(DMODEL), 256>>>((const uint2*)pycat2, YCAT2LD,
                                     (const uint2*)pG2, G2LD,
                                     p_ymid, DMODEL, DMODEL, FCOLS, nullptr, 0,
                                     nullptr, 0, 0, 0);
    // 11) RMSNorm + residual
    k_norm<<<MTOT, 128>>>(x, norm_w, out);
}